// round 5
// baseline (speedup 1.0000x reference)
#include <cuda_runtime.h>
#include <cstdint>

#define Bq 4
#define Tq 12
#define Nq 4096
#define Fq 32

// ---------------------------------------------------------------------------
// PTX helpers — Ampere-era only (compute_103-safe)
// ---------------------------------------------------------------------------
__device__ __forceinline__ uint32_t smem_to_u32(const void* p) {
    uint32_t a;
    asm("{ .reg .u64 t; cvta.to.shared.u64 t, %1; cvt.u32.u64 %0, t; }" : "=r"(a) : "l"(p));
    return a;
}

#define CP_ASYNC16(dst, src) \
    asm volatile("cp.async.cg.shared.global [%0], [%1], 16;" :: "r"(dst), "l"(src) : "memory")
#define CP_COMMIT() asm volatile("cp.async.commit_group;" ::: "memory")
#define CP_WAIT0()  asm volatile("cp.async.wait_group 0;" ::: "memory")
#define CP_WAIT1()  asm volatile("cp.async.wait_group 1;" ::: "memory")

__device__ __forceinline__ void ldsm4(uint32_t addr, uint32_t* r) {
    asm volatile("ldmatrix.sync.aligned.m8n8.x4.shared.b16 {%0,%1,%2,%3}, [%4];"
                 : "=r"(r[0]), "=r"(r[1]), "=r"(r[2]), "=r"(r[3]) : "r"(addr));
}
// s8 IMMA: D(s32) += A(s8,16x32) * B(s8,32x8)
__device__ __forceinline__ void imma(int* d, const uint32_t* a, uint32_t b0, uint32_t b1) {
    asm volatile("mma.sync.aligned.m16n8k32.row.col.s32.s8.s8.s32 "
                 "{%0,%1,%2,%3},{%4,%5,%6,%7},{%8,%9},{%0,%1,%2,%3};"
                 : "+r"(d[0]), "+r"(d[1]), "+r"(d[2]), "+r"(d[3])
                 : "r"(a[0]), "r"(a[1]), "r"(a[2]), "r"(a[3]), "r"(b0), "r"(b1));
}

// ---------------------------------------------------------------------------
// Device scratch
// ---------------------------------------------------------------------------
__device__ __align__(128) int8_t g_A8h[(size_t)Bq * Nq * Nq];
__device__ __align__(128) int8_t g_A8l[(size_t)Bq * Nq * Nq];
__device__ __align__(128) int8_t g_x8h[(size_t)Bq * Tq * Fq * Nq];  // [b][t*32+f][n]
__device__ __align__(128) int8_t g_x8l[(size_t)Bq * Tq * Fq * Nq];
__device__ __align__(128) int8_t g_S8h[(size_t)Bq * 2 * Fq * Nq];   // [b][64][n]  (h|m)
__device__ __align__(128) int8_t g_S8l[(size_t)Bq * 2 * Fq * Nq];
__device__ __align__(128) int8_t g_h8h[(size_t)Bq * Fq * Nq];       // [b][32][n]  (h_mid)
__device__ __align__(128) int8_t g_h8l[(size_t)Bq * Fq * Nq];

__device__ __align__(128) float g_YX[(size_t)Bq * Tq * Nq * Fq];
__device__ __align__(128) float g_Y1[4 * (size_t)Bq * Nq * 2 * Fq];  // split-K=4 partials
__device__ __align__(128) float g_Y2[4 * (size_t)Bq * Nq * Fq];
__device__ __align__(128) float g_m [(size_t)Bq * Nq * Fq];
__device__ __align__(128) float g_c [(size_t)Bq * Nq * Fq];

__device__ __forceinline__ float sigf(float x) { return 1.0f / (1.0f + __expf(-x)); }

// quantize v*scale to 15-bit signed, split as q = qh*128 + ql (both s8)
__device__ __forceinline__ void quant14(float v, float scale, int8_t& qh, int8_t& ql) {
    int q = __float2int_rn(v * scale);
    q = max(-16384, min(16383, q));
    int h = (q + 64) >> 7;
    h = min(127, h);
    qh = (int8_t)h;
    ql = (int8_t)(q - (h << 7));
}

// ---------------------------------------------------------------------------
// adj -> s8 hi/lo split, scale 2^25 (adj in [0, 1/4096] -> q in [0, 8192])
// ---------------------------------------------------------------------------
__global__ __launch_bounds__(256) void convert_adj(const float* __restrict__ adj) {
    size_t i = (size_t)blockIdx.x * 256 + threadIdx.x;
    float4 v = ((const float4*)adj)[i];
    char4 hc, lc;
    quant14(v.x, 33554432.f, (int8_t&)hc.x, (int8_t&)lc.x);
    quant14(v.y, 33554432.f, (int8_t&)hc.y, (int8_t&)lc.y);
    quant14(v.z, 33554432.f, (int8_t&)hc.z, (int8_t&)lc.z);
    quant14(v.w, 33554432.f, (int8_t&)hc.w, (int8_t&)lc.w);
    ((char4*)g_A8h)[i] = hc;
    ((char4*)g_A8l)[i] = lc;
}

__global__ void init_state() {
    int i = blockIdx.x * blockDim.x + threadIdx.x;
    if (i < Bq * Nq * Fq) { g_m[i] = 1.0f; g_c[i] = 1.0f; }
    if (i < Bq * 2 * Fq * Nq) {
        g_S8h[i] = 127;   // 1.0 -> q=16383 = 127*128 + 127
        g_S8l[i] = 127;
    }
}

// ---------------------------------------------------------------------------
// transpose + s8 split for x: [z][4096][32] fp32 -> [z][32][4096] s8 hi/lo
// x scale 2^11 (covers |x| <= 8)
// ---------------------------------------------------------------------------
__global__ __launch_bounds__(256) void trans_split_x(const float* __restrict__ V,
                                                     int8_t* __restrict__ Th,
                                                     int8_t* __restrict__ Tl) {
    __shared__ float tile[64][33];
    const int z = blockIdx.z;
    const int n0 = blockIdx.x * 64;
    const float* v = V + (size_t)z * Nq * 32 + (size_t)n0 * 32;
    const int tid = threadIdx.x;
#pragma unroll
    for (int idx = tid; idx < 64 * 32; idx += 256)
        tile[idx >> 5][idx & 31] = v[idx];
    __syncthreads();
    int8_t* th = Th + (size_t)z * 32 * Nq;
    int8_t* tl = Tl + (size_t)z * 32 * Nq;
#pragma unroll
    for (int idx = tid; idx < 64 * 32; idx += 256) {
        int f = idx >> 6, j = idx & 63;
        int8_t qh, ql;
        quant14(tile[j][f], 2048.f, qh, ql);
        th[(size_t)f * Nq + n0 + j] = qh;
        tl[(size_t)f * Nq + n0 + j] = ql;
    }
}

// ---------------------------------------------------------------------------
// int8 dual-word GEMM with split-K:
//   Y[part][z] = adj[z/adiv] @ V[z], scaled by outScale
// A/B stored as s8 pairs: value = (qh*128 + ql) / scale.
// D = (S_hh*2^14 + S_ml*2^7) * outScale,  S_ml = A_h*B_l + A_l*B_h (shared acc).
// BM=128, chunk K=64 (2 IMMA k-steps), 8 warps 4(m) x 2(n), 3-stage cp.async.
// MMA terms issued group-major (hh, hl, lh) -> dep distance 8 per accumulator.
// ---------------------------------------------------------------------------
template <int BN>
__global__ __launch_bounds__(256, 2) void adj_gemm_i8(
    const int8_t* __restrict__ Bh_g, const int8_t* __restrict__ Bl_g,
    long long bZ, int adiv, float* __restrict__ Y, long long yZ,
    int rstride, long long gstride, long long partStride, int nch, float outScale) {
    constexpr int RB = 80;                 // 64B k-data + 16B pad
    constexpr int A_BYTES = 128 * RB;      // 10240
    constexpr int B_BYTES = BN * RB;
    constexpr int OFF_AH = 0, OFF_AL = A_BYTES;
    constexpr int OFF_BH = 2 * A_BYTES, OFF_BL = 2 * A_BYTES + B_BYTES;
    constexpr int STAGE = 2 * A_BYTES + 2 * B_BYTES;
    constexpr int WN = BN / 2;
    constexpr int NF = WN / 8;             // 4 (BN=64) or 2 (BN=32)
    constexpr int NB = (NF + 1) / 2;       // 2 or 1

    extern __shared__ char smc[];
    const uint32_t sbase = smem_to_u32(smc);
    const int tid = threadIdx.x;
    const int wid = tid >> 5, lane = tid & 31;
    const int wm = wid & 3, wn = wid >> 2;
    const int z = blockIdx.z;
    const int m0 = blockIdx.x * 128;
    const int kbase = blockIdx.y * nch * 64;

    const int8_t* gAh = g_A8h + (size_t)(z / adiv) * Nq * Nq + (size_t)m0 * Nq + kbase;
    const int8_t* gAl = g_A8l + (size_t)(z / adiv) * Nq * Nq + (size_t)m0 * Nq + kbase;
    const int8_t* gBh = Bh_g + (size_t)z * bZ + kbase;
    const int8_t* gBl = Bl_g + (size_t)z * bZ + kbase;

    const bool bact = (BN == 64) || (tid < 128);

    int acc_hh[2][NF][4], acc_ml[2][NF][4];
#pragma unroll
    for (int mf = 0; mf < 2; mf++)
#pragma unroll
        for (int nf = 0; nf < NF; nf++)
#pragma unroll
            for (int q = 0; q < 4; q++) { acc_hh[mf][nf][q] = 0; acc_ml[mf][nf][q] = 0; }

    auto issue = [&](int c) {
        const uint32_t st = sbase + (uint32_t)(c % 3) * STAGE;
        const int k0 = c * 64;
        // A: 128 rows x 64B, hi+lo; 512 16B-chunks each, 2 per thread
#pragma unroll
        for (int rep = 0; rep < 2; rep++) {
            int idx = rep * 256 + tid;
            int r = idx >> 2, j = idx & 3;
            uint32_t d = st + r * RB + j * 16;
            CP_ASYNC16(d + OFF_AH, gAh + (size_t)r * Nq + k0 + j * 16);
            CP_ASYNC16(d + OFF_AL, gAl + (size_t)r * Nq + k0 + j * 16);
        }
        // B: BN rows x 64B, hi+lo
        if (bact) {
            int r = (BN == 64) ? (tid >> 2) : ((tid & 127) >> 2);
            int j = tid & 3;
            uint32_t d = st + r * RB + j * 16;
            CP_ASYNC16(d + OFF_BH, gBh + (size_t)r * Nq + k0 + j * 16);
            CP_ASYNC16(d + OFF_BL, gBl + (size_t)r * Nq + k0 + j * 16);
        }
    };

    issue(0); CP_COMMIT();
    issue(1); CP_COMMIT();

    // ldmatrix lane addressing (byte offsets within a tile):
    // A mats: (rows0-7,k0-15)(rows8-15,k0-15)(rows0-7,k16-31)(rows8-15,k16-31)
    const int a_r = (lane & 15);
    const int a_k = (lane >> 4) * 16;
    // B mats: (n0-7,k0)(n0-7,k16)(n8-15,k0)(n8-15,k16)
    const int b_r = ((lane >> 4) << 3) + (lane & 7);
    const int b_k = ((lane >> 3) & 1) * 16;

#pragma unroll 1
    for (int c = 0; c < nch; c++) {
        if (c + 1 < nch) { CP_WAIT1(); } else { CP_WAIT0(); }
        __syncthreads();
        if (c + 2 < nch) { issue(c + 2); CP_COMMIT(); }

        const uint32_t st = sbase + (uint32_t)(c % 3) * STAGE;
#pragma unroll
        for (int ks = 0; ks < 2; ks++) {
            const int kb = ks * 32;
            uint32_t ah[2][4], al[2][4];
#pragma unroll
            for (int mf = 0; mf < 2; mf++) {
                uint32_t addr = st + (wm * 32 + mf * 16 + a_r) * RB + kb + a_k;
                ldsm4(addr + OFF_AH, ah[mf]);
                ldsm4(addr + OFF_AL, al[mf]);
            }
            uint32_t bh[NB][4], bl[NB][4];
#pragma unroll
            for (int nb = 0; nb < NB; nb++) {
                uint32_t addr = st + (wn * WN + nb * 16 + b_r) * RB + kb + b_k;
                ldsm4(addr + OFF_BH, bh[nb]);
                ldsm4(addr + OFF_BL, bl[nb]);
            }
            // term group 1: hi*hi
#pragma unroll
            for (int mf = 0; mf < 2; mf++)
#pragma unroll
                for (int nf = 0; nf < NF; nf++) {
                    const int nb = nf >> 1, pr = (nf & 1) * 2;
                    imma(acc_hh[mf][nf], ah[mf], bh[nb][pr], bh[nb][pr + 1]);
                }
            // term group 2: hi*lo
#pragma unroll
            for (int mf = 0; mf < 2; mf++)
#pragma unroll
                for (int nf = 0; nf < NF; nf++) {
                    const int nb = nf >> 1, pr = (nf & 1) * 2;
                    imma(acc_ml[mf][nf], ah[mf], bl[nb][pr], bl[nb][pr + 1]);
                }
            // term group 3: lo*hi
#pragma unroll
            for (int mf = 0; mf < 2; mf++)
#pragma unroll
                for (int nf = 0; nf < NF; nf++) {
                    const int nb = nf >> 1, pr = (nf & 1) * 2;
                    imma(acc_ml[mf][nf], al[mf], bh[nb][pr], bh[nb][pr + 1]);
                }
        }
    }

    float* yb = Y + (size_t)blockIdx.y * partStride + (size_t)z * yZ;
#pragma unroll
    for (int mf = 0; mf < 2; mf++)
#pragma unroll
        for (int nf = 0; nf < NF; nf++) {
            int r = m0 + wm * 32 + mf * 16 + (lane >> 2);
            int cj = wn * WN + nf * 8 + (lane & 3) * 2;
            size_t off = (size_t)(cj >> 5) * gstride + (cj & 31);
            float* o0 = yb + (size_t)r * rstride + off;
            float* o1 = yb + (size_t)(r + 8) * rstride + off;
            float v0 = ((float)acc_hh[mf][nf][0] * 16384.f + (float)acc_ml[mf][nf][0] * 128.f) * outScale;
            float v1 = ((float)acc_hh[mf][nf][1] * 16384.f + (float)acc_ml[mf][nf][1] * 128.f) * outScale;
            float v2 = ((float)acc_hh[mf][nf][2] * 16384.f + (float)acc_ml[mf][nf][2] * 128.f) * outScale;
            float v3 = ((float)acc_hh[mf][nf][3] * 16384.f + (float)acc_ml[mf][nf][3] * 128.f) * outScale;
            *(float2*)o0 = make_float2(v0, v1);
            *(float2*)o1 = make_float2(v2, v3);
        }
}

// ---------------------------------------------------------------------------
// gates1: LSTM gates 0..7; sums 4 split-K partials of Y1; writes h_mid as
// transposed s8 hi/lo (scale 2^14) for the next GEMM.
// ---------------------------------------------------------------------------
__global__ __launch_bounds__(256) void gates1_kernel(const float* __restrict__ W,
                                                     const float* __restrict__ bias,
                                                     int t, float* __restrict__ last_c) {
    extern __shared__ float sm[];
    float4* Wp = (float4*)sm;
    float4* bp = (float4*)(sm + 16384);
    const long long PS1 = (long long)Bq * Nq * 64;

    const int tid = threadIdx.x;
    for (int idx = tid; idx < 4096; idx += 256) {
        int l = idx & 31, p = (idx >> 5) & 3, k = idx >> 7;
        const float* W0 = W + (2 * p) * (Fq * 2 * Fq) + k * (2 * Fq);
        const float* W1 = W + (2 * p + 1) * (Fq * 2 * Fq) + k * (2 * Fq);
        Wp[idx] = make_float4(W0[l], W0[l + 32], W1[l], W1[l + 32]);
    }
    if (tid < 128) {
        int l = tid & 31, p = tid >> 5;
        bp[p * 32 + l] = make_float4(bias[(2 * p) * 64 + l], bias[(2 * p) * 64 + 32 + l],
                                     bias[(2 * p + 1) * 64 + l], bias[(2 * p + 1) * 64 + 32 + l]);
    }
    __syncthreads();

    const int w = tid >> 5, l = tid & 31;
    const int nrows = Bq * Nq;
    for (int row = blockIdx.x * 8 + w; row < nrows; row += gridDim.x * 8) {
        int b = row >> 12, n = row & (Nq - 1);
        float yx = g_YX[(((size_t)b * Tq + t) * Nq + n) * Fq + l];
        float yh = 0.f;
#pragma unroll
        for (int p = 0; p < 4; p++) yh += g_Y1[p * PS1 + (size_t)row * 64 + l];

        float acc[4][4];
#pragma unroll
        for (int p = 0; p < 4; p++)
#pragma unroll
            for (int q = 0; q < 4; q++) acc[p][q] = 0.0f;

#pragma unroll
        for (int k = 0; k < 32; k++) {
            float ykx = __shfl_sync(0xffffffffu, yx, k);
            float ykh = __shfl_sync(0xffffffffu, yh, k);
#pragma unroll
            for (int p = 0; p < 4; p++) {
                float4 wv = Wp[k * 128 + p * 32 + l];
                acc[p][0] = fmaf(ykx, wv.x, acc[p][0]);
                acc[p][1] = fmaf(ykx, wv.y, acc[p][1]);
                acc[p][2] = fmaf(ykh, wv.z, acc[p][2]);
                acc[p][3] = fmaf(ykh, wv.w, acc[p][3]);
            }
        }

        float s[4];
#pragma unroll
        for (int p = 0; p < 4; p++) {
            float4 bb = bp[p * 32 + l];
            float gx = (acc[p][0] + bb.x) * sigf(acc[p][1] + bb.y);
            float gh = (acc[p][2] + bb.z) * sigf(acc[p][3] + bb.w);
            s[p] = gx + gh;
        }
        float f  = sigf(s[0]);
        float ig = sigf(s[1]);
        float o  = sigf(s[3]);
        size_t ci = (size_t)row * Fq + l;
        float cn = f * g_c[ci] + ig * tanhf(s[2]);
        g_c[ci] = cn;
        float hm = o * tanhf(cn);
        size_t ti = ((size_t)b * Fq + l) * Nq + n;
        int8_t qh, ql;
        quant14(hm, 16384.f, qh, ql);
        g_h8h[ti] = qh;
        g_h8l[ti] = ql;
        if (t == Tq - 1) last_c[ci] = cn;
    }
}

// ---------------------------------------------------------------------------
// gates2: memory gates 8..13; sums 4 partials of Y2 and Y1's m-half;
// writes new [h|m] transposed s8 hi/lo.
// ---------------------------------------------------------------------------
__global__ __launch_bounds__(256) void gates2_kernel(const float* __restrict__ W8,
                                                     const float* __restrict__ bias8,
                                                     int t, float* __restrict__ hidden,
                                                     float* __restrict__ last_h,
                                                     float* __restrict__ last_m) {
    extern __shared__ float sm[];
    float4* Wp = (float4*)sm;
    float4* bp = (float4*)(sm + 12288);
    const long long PS1 = (long long)Bq * Nq * 64;
    const long long PS2 = (long long)Bq * Nq * 32;

    const int tid = threadIdx.x;
    for (int idx = tid; idx < 3072; idx += 256) {
        int k = idx / 96, r = idx % 96, p = r >> 5, l = r & 31;
        const float* W0 = W8 + (2 * p) * (Fq * 2 * Fq) + k * (2 * Fq);
        const float* W1 = W8 + (2 * p + 1) * (Fq * 2 * Fq) + k * (2 * Fq);
        Wp[idx] = make_float4(W0[l], W0[l + 32], W1[l], W1[l + 32]);
    }
    if (tid < 96) {
        int p = tid >> 5, l = tid & 31;
        bp[tid] = make_float4(bias8[(2 * p) * 64 + l], bias8[(2 * p) * 64 + 32 + l],
                              bias8[(2 * p + 1) * 64 + l], bias8[(2 * p + 1) * 64 + 32 + l]);
    }
    __syncthreads();

    const int w = tid >> 5, l = tid & 31;
    const int nrows = Bq * Nq;
    for (int row = blockIdx.x * 8 + w; row < nrows; row += gridDim.x * 8) {
        int b = row >> 12, n = row & (Nq - 1);
        float y2 = 0.f, ym = 0.f;
#pragma unroll
        for (int p = 0; p < 4; p++) {
            y2 += g_Y2[p * PS2 + (size_t)row * 32 + l];
            ym += g_Y1[p * PS1 + (size_t)row * 64 + 32 + l];
        }

        float acc[3][4];
#pragma unroll
        for (int p = 0; p < 3; p++)
#pragma unroll
            for (int q = 0; q < 4; q++) acc[p][q] = 0.0f;

#pragma unroll
        for (int k = 0; k < 32; k++) {
            float yk2 = __shfl_sync(0xffffffffu, y2, k);
            float ykm = __shfl_sync(0xffffffffu, ym, k);
#pragma unroll
            for (int p = 0; p < 3; p++) {
                float4 wv = Wp[k * 96 + p * 32 + l];
                acc[p][0] = fmaf(yk2, wv.x, acc[p][0]);
                acc[p][1] = fmaf(yk2, wv.y, acc[p][1]);
                acc[p][2] = fmaf(ykm, wv.z, acc[p][2]);
                acc[p][3] = fmaf(ykm, wv.w, acc[p][3]);
            }
        }

        float s[3];
#pragma unroll
        for (int p = 0; p < 3; p++) {
            float4 bb = bp[p * 32 + l];
            float gx = (acc[p][0] + bb.x) * sigf(acc[p][1] + bb.y);
            float gh = (acc[p][2] + bb.z) * sigf(acc[p][3] + bb.w);
            s[p] = gx + gh;
        }
        float i2 = sigf(s[0]);
        float gg = sigf(s[1]);
        float o2 = sigf(s[2]);
        size_t ci = (size_t)row * Fq + l;
        float mo = g_m[ci];
        float mn = i2 * mo + (1.0f - i2) * gg;
        float hn = mn * o2;
        g_m[ci] = mn;
        size_t th = ((size_t)b * 64 + l) * Nq + n;
        size_t tm = ((size_t)b * 64 + 32 + l) * Nq + n;
        int8_t qh, ql;
        quant14(hn, 16384.f, qh, ql);
        g_S8h[th] = qh; g_S8l[th] = ql;
        quant14(mn, 16384.f, qh, ql);
        g_S8h[tm] = qh; g_S8l[tm] = ql;
        hidden[(((size_t)b * Tq + t) * Nq + n) * Fq + l] = hn;
        if (t == Tq - 1) {
            last_h[ci] = hn;
            last_m[ci] = mn;
        }
    }
}

// ---------------------------------------------------------------------------
// kernel_launch
// ---------------------------------------------------------------------------
extern "C" void kernel_launch(void* const* d_in, const int* in_sizes, int n_in,
                              void* d_out, int out_size) {
    (void)in_sizes; (void)n_in; (void)out_size;
    const float* x    = (const float*)d_in[0];
    const float* adj  = (const float*)d_in[1];
    const float* W    = (const float*)d_in[2];
    const float* bias = (const float*)d_in[3];

    float* hidden = (float*)d_out;
    float* last_h = hidden + (size_t)Bq * Tq * Nq * Fq;
    float* last_c = last_h + (size_t)Bq * Nq * Fq;
    float* last_m = last_c + (size_t)Bq * Nq * Fq;

    float *pYX, *pY1, *pY2;
    int8_t *px8h, *px8l, *pS8h, *pS8l, *ph8h, *ph8l;
    cudaGetSymbolAddress((void**)&pYX,  g_YX);
    cudaGetSymbolAddress((void**)&pY1,  g_Y1);
    cudaGetSymbolAddress((void**)&pY2,  g_Y2);
    cudaGetSymbolAddress((void**)&px8h, g_x8h);
    cudaGetSymbolAddress((void**)&px8l, g_x8l);
    cudaGetSymbolAddress((void**)&pS8h, g_S8h);
    cudaGetSymbolAddress((void**)&pS8l, g_S8l);
    cudaGetSymbolAddress((void**)&ph8h, g_h8h);
    cudaGetSymbolAddress((void**)&ph8l, g_h8l);

    const int G1_SMEM = (16384 + 512) * 4;
    const int G2_SMEM = (12288 + 384) * 4;
    const int GEMM64_SMEM = 3 * (2 * 128 * 80 + 2 * 64 * 80);  // 92160
    const int GEMM32_SMEM = 3 * (2 * 128 * 80 + 2 * 32 * 80);  // 76800
    cudaFuncSetAttribute(gates1_kernel, cudaFuncAttributeMaxDynamicSharedMemorySize, G1_SMEM);
    cudaFuncSetAttribute(gates2_kernel, cudaFuncAttributeMaxDynamicSharedMemorySize, G2_SMEM);
    cudaFuncSetAttribute(adj_gemm_i8<64>, cudaFuncAttributeMaxDynamicSharedMemorySize, GEMM64_SMEM);
    cudaFuncSetAttribute(adj_gemm_i8<32>, cudaFuncAttributeMaxDynamicSharedMemorySize, GEMM32_SMEM);

    convert_adj<<<(Bq * Nq * Nq / 4) / 256, 256>>>(adj);
    init_state<<<(Bq * 2 * Fq * Nq + 255) / 256, 256>>>();
    trans_split_x<<<dim3(Nq / 64, 1, Bq * Tq), 256>>>(x, px8h, px8l);

    // scales: A=2^25; x=2^11 -> 1/2^36; state=2^14 -> 1/2^39
    const float SCL_X = 1.f / 68719476736.f;     // 2^-36
    const float SCL_S = 1.f / 549755813888.f;    // 2^-39

    // Precompute adj @ x: 24 slabs of BN=64 (t-pairs), full-K (nch=64), adiv=6
    adj_gemm_i8<64><<<dim3(Nq / 128, 1, Bq * Tq / 2), 256, GEMM64_SMEM>>>(
        px8h, px8l, (long long)64 * Nq, 6,
        pYX, (long long)Nq * 64, 32, (long long)Nq * 32, 0LL, 64, SCL_X);

    const long long PS1 = (long long)Bq * Nq * 64;
    const long long PS2 = (long long)Bq * Nq * 32;
    for (int t = 0; t < Tq; t++) {
        // Y1 = adj @ [h|m]^T   (split-K=4, nch=16)
        adj_gemm_i8<64><<<dim3(Nq / 128, 4, Bq), 256, GEMM64_SMEM>>>(
            pS8h, pS8l, (long long)64 * Nq, 1, pY1, (long long)Nq * 64,
            64, 32LL, PS1, 16, SCL_S);
        gates1_kernel<<<512, 256, G1_SMEM>>>(W, bias, t, last_c);
        // Y2 = adj @ h_mid^T   (split-K=4, nch=16)
        adj_gemm_i8<32><<<dim3(Nq / 128, 4, Bq), 256, GEMM32_SMEM>>>(
            ph8h, ph8l, (long long)32 * Nq, 1, pY2, (long long)Nq * 32,
            32, 32LL, PS2, 16, SCL_S);
        gates2_kernel<<<512, 256, G2_SMEM>>>(W + 8 * (Fq * 2 * Fq), bias + 8 * (2 * Fq),
                                             t, hidden, last_h, last_m);
    }
}

// round 6
// speedup vs baseline: 1.1509x; 1.1509x over previous
#include <cuda_runtime.h>
#include <cuda_bf16.h>
#include <cstdint>

#define Bq 4
#define Tq 12
#define Nq 4096
#define Fq 32

// ---------------------------------------------------------------------------
// PTX helpers — Ampere-era only (compute_103-safe; tcgen05 rejected by ptxas
// at the harness's compute_103 virtual arch, s8 IMMA measured slow on R5)
// ---------------------------------------------------------------------------
__device__ __forceinline__ uint32_t smem_to_u32(const void* p) {
    uint32_t a;
    asm("{ .reg .u64 t; cvta.to.shared.u64 t, %1; cvt.u32.u64 %0, t; }" : "=r"(a) : "l"(p));
    return a;
}

#define CP_ASYNC16(dst, src) \
    asm volatile("cp.async.cg.shared.global [%0], [%1], 16;" :: "r"(dst), "l"(src) : "memory")
#define CP_COMMIT() asm volatile("cp.async.commit_group;" ::: "memory")
#define CP_WAIT0()  asm volatile("cp.async.wait_group 0;" ::: "memory")
#define CP_WAIT1()  asm volatile("cp.async.wait_group 1;" ::: "memory")

__device__ __forceinline__ void ldsm4(uint32_t addr, uint32_t* r) {
    asm volatile("ldmatrix.sync.aligned.m8n8.x4.shared.b16 {%0,%1,%2,%3}, [%4];"
                 : "=r"(r[0]), "=r"(r[1]), "=r"(r[2]), "=r"(r[3]) : "r"(addr));
}
__device__ __forceinline__ void mma16816(float* d, const uint32_t* a, uint32_t b0, uint32_t b1) {
    asm volatile("mma.sync.aligned.m16n8k16.row.col.f32.bf16.bf16.f32 "
                 "{%0,%1,%2,%3},{%4,%5,%6,%7},{%8,%9},{%0,%1,%2,%3};"
                 : "+f"(d[0]), "+f"(d[1]), "+f"(d[2]), "+f"(d[3])
                 : "r"(a[0]), "r"(a[1]), "r"(a[2]), "r"(a[3]), "r"(b0), "r"(b1));
}

// ---------------------------------------------------------------------------
// Device scratch
// ---------------------------------------------------------------------------
__device__ __align__(128) __nv_bfloat16 g_Ahi[(size_t)Bq * Nq * Nq];
__device__ __align__(128) __nv_bfloat16 g_Alo[(size_t)Bq * Nq * Nq];
__device__ __align__(128) __nv_bfloat16 g_xth[(size_t)Bq * Tq * Fq * Nq];  // [b][t*32+f][n]
__device__ __align__(128) __nv_bfloat16 g_xtl[(size_t)Bq * Tq * Fq * Nq];
__device__ __align__(128) __nv_bfloat16 g_Sth[(size_t)Bq * 2 * Fq * Nq];   // [b][64][n]  (h|m)
__device__ __align__(128) __nv_bfloat16 g_Stl[(size_t)Bq * 2 * Fq * Nq];
__device__ __align__(128) __nv_bfloat16 g_hth[(size_t)Bq * Fq * Nq];       // [b][32][n]  (h_mid)
__device__ __align__(128) __nv_bfloat16 g_htl[(size_t)Bq * Fq * Nq];

__device__ __align__(128) float g_YX[(size_t)Bq * Tq * Nq * Fq];
__device__ __align__(128) float g_Y1[4 * (size_t)Bq * Nq * 2 * Fq];  // split-K=4 partials
__device__ __align__(128) float g_Y2[4 * (size_t)Bq * Nq * Fq];
__device__ __align__(128) float g_m [(size_t)Bq * Nq * Fq];
__device__ __align__(128) float g_c [(size_t)Bq * Nq * Fq];

__device__ __forceinline__ float sigf(float x) { return 1.0f / (1.0f + __expf(-x)); }

// ---------------------------------------------------------------------------
// adj -> bf16 hi/lo split
// ---------------------------------------------------------------------------
__global__ __launch_bounds__(256) void convert_adj(const float* __restrict__ adj) {
    size_t i = (size_t)blockIdx.x * 256 + threadIdx.x;
    float4 v = ((const float4*)adj)[i];
    __nv_bfloat16 h0 = __float2bfloat16(v.x), h1 = __float2bfloat16(v.y);
    __nv_bfloat16 h2 = __float2bfloat16(v.z), h3 = __float2bfloat16(v.w);
    __nv_bfloat16 l0 = __float2bfloat16(v.x - __bfloat162float(h0));
    __nv_bfloat16 l1 = __float2bfloat16(v.y - __bfloat162float(h1));
    __nv_bfloat16 l2 = __float2bfloat16(v.z - __bfloat162float(h2));
    __nv_bfloat16 l3 = __float2bfloat16(v.w - __bfloat162float(h3));
    __nv_bfloat162 hp0 = {h0, h1}, hp1 = {h2, h3}, lp0 = {l0, l1}, lp1 = {l2, l3};
    uint2 hw, lw;
    hw.x = *(uint32_t*)&hp0; hw.y = *(uint32_t*)&hp1;
    lw.x = *(uint32_t*)&lp0; lw.y = *(uint32_t*)&lp1;
    ((uint2*)g_Ahi)[i] = hw;
    ((uint2*)g_Alo)[i] = lw;
}

__global__ void init_state() {
    int i = blockIdx.x * blockDim.x + threadIdx.x;
    if (i < Bq * Nq * Fq) { g_m[i] = 1.0f; g_c[i] = 1.0f; }
    if (i < Bq * 2 * Fq * Nq) {
        g_Sth[i] = __float2bfloat16(1.0f);
        g_Stl[i] = __float2bfloat16(0.0f);
    }
}

// ---------------------------------------------------------------------------
// transpose + bf16 split for x: [z][4096][32] fp32 -> [z][32][4096] bf16 hi/lo
// ---------------------------------------------------------------------------
__global__ __launch_bounds__(256) void trans_split_x(const float* __restrict__ V,
                                                     __nv_bfloat16* __restrict__ Thi,
                                                     __nv_bfloat16* __restrict__ Tlo) {
    __shared__ float tile[64][33];
    const int z = blockIdx.z;
    const int n0 = blockIdx.x * 64;
    const float* v = V + (size_t)z * Nq * 32 + (size_t)n0 * 32;
    const int tid = threadIdx.x;
#pragma unroll
    for (int idx = tid; idx < 64 * 32; idx += 256)
        tile[idx >> 5][idx & 31] = v[idx];
    __syncthreads();
    __nv_bfloat16* th = Thi + (size_t)z * 32 * Nq;
    __nv_bfloat16* tl = Tlo + (size_t)z * 32 * Nq;
#pragma unroll
    for (int idx = tid; idx < 64 * 32; idx += 256) {
        int f = idx >> 6, j = idx & 63;
        float val = tile[j][f];
        __nv_bfloat16 hi = __float2bfloat16(val);
        __nv_bfloat16 lo = __float2bfloat16(val - __bfloat162float(hi));
        th[(size_t)f * Nq + n0 + j] = hi;
        tl[(size_t)f * Nq + n0 + j] = lo;
    }
}

// ---------------------------------------------------------------------------
// split-bf16 mma.sync GEMM with split-K:
//   Y[part=blockIdx.y][z] = adj[z/adiv][kseg] @ V[z][kseg]
// D = Ahi*Bhi + Ahi*Blo + Alo*Bhi, fp32 register accumulators.
// BM=128, BK=32, 8 warps 4(m) x 2(n), 3-stage cp.async, single barrier/chunk.
// MMA issue is TERM-MAJOR (all hh, all hl, all lh): dependent reuse distance
// per accumulator = 2*NF instead of 1 -> hides HMMA latency (R4: issue=16.6%).
// ---------------------------------------------------------------------------
template <int BN>
__global__ __launch_bounds__(256, 2) void adj_gemm_mma(
    const __nv_bfloat16* __restrict__ Bhi_g, const __nv_bfloat16* __restrict__ Blo_g,
    long long bZ, int adiv, float* __restrict__ Y, long long yZ,
    int rstride, long long gstride, long long partStride, int nch) {
    constexpr int RB = 80;                 // 64B data + 16B pad
    constexpr int A_BYTES = 128 * RB;
    constexpr int B_BYTES = BN * RB;
    constexpr int OFF_AH = 0, OFF_AL = A_BYTES;
    constexpr int OFF_BH = 2 * A_BYTES, OFF_BL = 2 * A_BYTES + B_BYTES;
    constexpr int STAGE = 2 * A_BYTES + 2 * B_BYTES;
    constexpr int WN = BN / 2;
    constexpr int NF = WN / 8;
    constexpr int NB = (NF + 1) / 2;

    extern __shared__ char smc[];
    const uint32_t sbase = smem_to_u32(smc);
    const int tid = threadIdx.x;
    const int wid = tid >> 5, lane = tid & 31;
    const int wm = wid & 3, wn = wid >> 2;
    const int z = blockIdx.z;
    const int m0 = blockIdx.x * 128;
    const int kbase = blockIdx.y * nch * 32;

    const __nv_bfloat16* gAh = g_Ahi + (size_t)(z / adiv) * Nq * Nq + (size_t)m0 * Nq + kbase;
    const __nv_bfloat16* gAl = g_Alo + (size_t)(z / adiv) * Nq * Nq + (size_t)m0 * Nq + kbase;
    const __nv_bfloat16* gBh = Bhi_g + (size_t)z * bZ + kbase;
    const __nv_bfloat16* gBl = Blo_g + (size_t)z * bZ + kbase;

    const int arow = tid >> 2;
    const int acol = tid & 3;
    const int brow = tid >> 2;
    const bool bact = (BN == 64) || (tid < 128);

    float acc[2][NF][4];
#pragma unroll
    for (int mf = 0; mf < 2; mf++)
#pragma unroll
        for (int nf = 0; nf < NF; nf++)
#pragma unroll
            for (int q = 0; q < 4; q++) acc[mf][nf][q] = 0.0f;

    auto issue = [&](int c) {
        const uint32_t st = sbase + (uint32_t)(c % 3) * STAGE;
        const int k0 = c * 32;
#pragma unroll
        for (int rep = 0; rep < 2; rep++) {
            int r = rep * 64 + arow;
            uint32_t d = st + r * RB + acol * 16;
            CP_ASYNC16(d + OFF_AH, gAh + (size_t)r * Nq + k0 + acol * 8);
            CP_ASYNC16(d + OFF_AL, gAl + (size_t)r * Nq + k0 + acol * 8);
        }
        if (bact) {
            uint32_t d = st + brow * RB + acol * 16;
            CP_ASYNC16(d + OFF_BH, gBh + (size_t)brow * Nq + k0 + acol * 8);
            CP_ASYNC16(d + OFF_BL, gBl + (size_t)brow * Nq + k0 + acol * 8);
        }
    };

    issue(0); CP_COMMIT();
    issue(1); CP_COMMIT();

    const int a_r = (lane & 15);
    const int a_k = (lane >> 4) * 16;
    const int b_r = ((lane >> 4) << 3) + (lane & 7);
    const int b_k = ((lane >> 3) & 1) * 16;

#pragma unroll 1
    for (int c = 0; c < nch; c++) {
        if (c + 1 < nch) { CP_WAIT1(); } else { CP_WAIT0(); }
        __syncthreads();
        if (c + 2 < nch) { issue(c + 2); CP_COMMIT(); }

        const uint32_t st = sbase + (uint32_t)(c % 3) * STAGE;
#pragma unroll
        for (int ks = 0; ks < 2; ks++) {
            uint32_t ah[2][4], al[2][4];
#pragma unroll
            for (int mf = 0; mf < 2; mf++) {
                uint32_t addr = st + (wm * 32 + mf * 16 + a_r) * RB + ks * 32 + a_k;
                ldsm4(addr + OFF_AH, ah[mf]);
                ldsm4(addr + OFF_AL, al[mf]);
            }
            uint32_t bh[NB][4], bl[NB][4];
#pragma unroll
            for (int nb = 0; nb < NB; nb++) {
                uint32_t addr = st + (wn * WN + nb * 16 + b_r) * RB + ks * 32 + b_k;
                ldsm4(addr + OFF_BH, bh[nb]);
                ldsm4(addr + OFF_BL, bl[nb]);
            }
            // term group 1: Ahi * Bhi  (2*NF independent MMAs)
#pragma unroll
            for (int mf = 0; mf < 2; mf++)
#pragma unroll
                for (int nf = 0; nf < NF; nf++) {
                    const int nb = nf >> 1, pr = (nf & 1) * 2;
                    mma16816(acc[mf][nf], ah[mf], bh[nb][pr], bh[nb][pr + 1]);
                }
            // term group 2: Ahi * Blo
#pragma unroll
            for (int mf = 0; mf < 2; mf++)
#pragma unroll
                for (int nf = 0; nf < NF; nf++) {
                    const int nb = nf >> 1, pr = (nf & 1) * 2;
                    mma16816(acc[mf][nf], ah[mf], bl[nb][pr], bl[nb][pr + 1]);
                }
            // term group 3: Alo * Bhi
#pragma unroll
            for (int mf = 0; mf < 2; mf++)
#pragma unroll
                for (int nf = 0; nf < NF; nf++) {
                    const int nb = nf >> 1, pr = (nf & 1) * 2;
                    mma16816(acc[mf][nf], al[mf], bh[nb][pr], bh[nb][pr + 1]);
                }
        }
    }

    float* yb = Y + (size_t)blockIdx.y * partStride + (size_t)z * yZ;
#pragma unroll
    for (int mf = 0; mf < 2; mf++)
#pragma unroll
        for (int nf = 0; nf < NF; nf++) {
            int r = m0 + wm * 32 + mf * 16 + (lane >> 2);
            int cj = wn * WN + nf * 8 + (lane & 3) * 2;
            size_t off = (size_t)(cj >> 5) * gstride + (cj & 31);
            float* o0 = yb + (size_t)r * rstride + off;
            float* o1 = yb + (size_t)(r + 8) * rstride + off;
            *(float2*)o0 = make_float2(acc[mf][nf][0], acc[mf][nf][1]);
            *(float2*)o1 = make_float2(acc[mf][nf][2], acc[mf][nf][3]);
        }
}

// ---------------------------------------------------------------------------
// gates1: LSTM gates 0..7; sums 4 split-K partials; writes h_mid transposed
// as bf16 hi/lo.
// ---------------------------------------------------------------------------
__global__ __launch_bounds__(256) void gates1_kernel(const float* __restrict__ W,
                                                     const float* __restrict__ bias,
                                                     int t, float* __restrict__ last_c) {
    extern __shared__ float sm[];
    float4* Wp = (float4*)sm;
    float4* bp = (float4*)(sm + 16384);
    const long long PS1 = (long long)Bq * Nq * 64;

    const int tid = threadIdx.x;
    for (int idx = tid; idx < 4096; idx += 256) {
        int l = idx & 31, p = (idx >> 5) & 3, k = idx >> 7;
        const float* W0 = W + (2 * p) * (Fq * 2 * Fq) + k * (2 * Fq);
        const float* W1 = W + (2 * p + 1) * (Fq * 2 * Fq) + k * (2 * Fq);
        Wp[idx] = make_float4(W0[l], W0[l + 32], W1[l], W1[l + 32]);
    }
    if (tid < 128) {
        int l = tid & 31, p = tid >> 5;
        bp[p * 32 + l] = make_float4(bias[(2 * p) * 64 + l], bias[(2 * p) * 64 + 32 + l],
                                     bias[(2 * p + 1) * 64 + l], bias[(2 * p + 1) * 64 + 32 + l]);
    }
    __syncthreads();

    const int w = tid >> 5, l = tid & 31;
    const int nrows = Bq * Nq;
    for (int row = blockIdx.x * 8 + w; row < nrows; row += gridDim.x * 8) {
        int b = row >> 12, n = row & (Nq - 1);
        float yx = g_YX[(((size_t)b * Tq + t) * Nq + n) * Fq + l];
        float yh = 0.f;
#pragma unroll
        for (int p = 0; p < 4; p++) yh += g_Y1[p * PS1 + (size_t)row * 64 + l];

        float acc[4][4];
#pragma unroll
        for (int p = 0; p < 4; p++)
#pragma unroll
            for (int q = 0; q < 4; q++) acc[p][q] = 0.0f;

#pragma unroll
        for (int k = 0; k < 32; k++) {
            float ykx = __shfl_sync(0xffffffffu, yx, k);
            float ykh = __shfl_sync(0xffffffffu, yh, k);
#pragma unroll
            for (int p = 0; p < 4; p++) {
                float4 wv = Wp[k * 128 + p * 32 + l];
                acc[p][0] = fmaf(ykx, wv.x, acc[p][0]);
                acc[p][1] = fmaf(ykx, wv.y, acc[p][1]);
                acc[p][2] = fmaf(ykh, wv.z, acc[p][2]);
                acc[p][3] = fmaf(ykh, wv.w, acc[p][3]);
            }
        }

        float s[4];
#pragma unroll
        for (int p = 0; p < 4; p++) {
            float4 bb = bp[p * 32 + l];
            float gx = (acc[p][0] + bb.x) * sigf(acc[p][1] + bb.y);
            float gh = (acc[p][2] + bb.z) * sigf(acc[p][3] + bb.w);
            s[p] = gx + gh;
        }
        float f  = sigf(s[0]);
        float ig = sigf(s[1]);
        float o  = sigf(s[3]);
        size_t ci = (size_t)row * Fq + l;
        float cn = f * g_c[ci] + ig * tanhf(s[2]);
        g_c[ci] = cn;
        float hm = o * tanhf(cn);
        size_t ti = ((size_t)b * Fq + l) * Nq + n;
        __nv_bfloat16 hi = __float2bfloat16(hm);
        g_hth[ti] = hi;
        g_htl[ti] = __float2bfloat16(hm - __bfloat162float(hi));
        if (t == Tq - 1) last_c[ci] = cn;
    }
}

// ---------------------------------------------------------------------------
// gates2: memory gates 8..13; sums 4 split-K partials; writes new [h|m]
// transposed bf16 hi/lo.
// ---------------------------------------------------------------------------
__global__ __launch_bounds__(256) void gates2_kernel(const float* __restrict__ W8,
                                                     const float* __restrict__ bias8,
                                                     int t, float* __restrict__ hidden,
                                                     float* __restrict__ last_h,
                                                     float* __restrict__ last_m) {
    extern __shared__ float sm[];
    float4* Wp = (float4*)sm;
    float4* bp = (float4*)(sm + 12288);
    const long long PS1 = (long long)Bq * Nq * 64;
    const long long PS2 = (long long)Bq * Nq * 32;

    const int tid = threadIdx.x;
    for (int idx = tid; idx < 3072; idx += 256) {
        int k = idx / 96, r = idx % 96, p = r >> 5, l = r & 31;
        const float* W0 = W8 + (2 * p) * (Fq * 2 * Fq) + k * (2 * Fq);
        const float* W1 = W8 + (2 * p + 1) * (Fq * 2 * Fq) + k * (2 * Fq);
        Wp[idx] = make_float4(W0[l], W0[l + 32], W1[l], W1[l + 32]);
    }
    if (tid < 96) {
        int p = tid >> 5, l = tid & 31;
        bp[tid] = make_float4(bias8[(2 * p) * 64 + l], bias8[(2 * p) * 64 + 32 + l],
                              bias8[(2 * p + 1) * 64 + l], bias8[(2 * p + 1) * 64 + 32 + l]);
    }
    __syncthreads();

    const int w = tid >> 5, l = tid & 31;
    const int nrows = Bq * Nq;
    for (int row = blockIdx.x * 8 + w; row < nrows; row += gridDim.x * 8) {
        int b = row >> 12, n = row & (Nq - 1);
        float y2 = 0.f, ym = 0.f;
#pragma unroll
        for (int p = 0; p < 4; p++) {
            y2 += g_Y2[p * PS2 + (size_t)row * 32 + l];
            ym += g_Y1[p * PS1 + (size_t)row * 64 + 32 + l];
        }

        float acc[3][4];
#pragma unroll
        for (int p = 0; p < 3; p++)
#pragma unroll
            for (int q = 0; q < 4; q++) acc[p][q] = 0.0f;

#pragma unroll
        for (int k = 0; k < 32; k++) {
            float yk2 = __shfl_sync(0xffffffffu, y2, k);
            float ykm = __shfl_sync(0xffffffffu, ym, k);
#pragma unroll
            for (int p = 0; p < 3; p++) {
                float4 wv = Wp[k * 96 + p * 32 + l];
                acc[p][0] = fmaf(yk2, wv.x, acc[p][0]);
                acc[p][1] = fmaf(yk2, wv.y, acc[p][1]);
                acc[p][2] = fmaf(ykm, wv.z, acc[p][2]);
                acc[p][3] = fmaf(ykm, wv.w, acc[p][3]);
            }
        }

        float s[3];
#pragma unroll
        for (int p = 0; p < 3; p++) {
            float4 bb = bp[p * 32 + l];
            float gx = (acc[p][0] + bb.x) * sigf(acc[p][1] + bb.y);
            float gh = (acc[p][2] + bb.z) * sigf(acc[p][3] + bb.w);
            s[p] = gx + gh;
        }
        float i2 = sigf(s[0]);
        float gg = sigf(s[1]);
        float o2 = sigf(s[2]);
        size_t ci = (size_t)row * Fq + l;
        float mo = g_m[ci];
        float mn = i2 * mo + (1.0f - i2) * gg;
        float hn = mn * o2;
        g_m[ci] = mn;
        size_t th = ((size_t)b * 64 + l) * Nq + n;
        size_t tm = ((size_t)b * 64 + 32 + l) * Nq + n;
        __nv_bfloat16 hh = __float2bfloat16(hn);
        __nv_bfloat16 mh = __float2bfloat16(mn);
        g_Sth[th] = hh;
        g_Stl[th] = __float2bfloat16(hn - __bfloat162float(hh));
        g_Sth[tm] = mh;
        g_Stl[tm] = __float2bfloat16(mn - __bfloat162float(mh));
        hidden[(((size_t)b * Tq + t) * Nq + n) * Fq + l] = hn;
        if (t == Tq - 1) {
            last_h[ci] = hn;
            last_m[ci] = mn;
        }
    }
}

// ---------------------------------------------------------------------------
// kernel_launch
// ---------------------------------------------------------------------------
extern "C" void kernel_launch(void* const* d_in, const int* in_sizes, int n_in,
                              void* d_out, int out_size) {
    (void)in_sizes; (void)n_in; (void)out_size;
    const float* x    = (const float*)d_in[0];
    const float* adj  = (const float*)d_in[1];
    const float* W    = (const float*)d_in[2];
    const float* bias = (const float*)d_in[3];

    float* hidden = (float*)d_out;
    float* last_h = hidden + (size_t)Bq * Tq * Nq * Fq;
    float* last_c = last_h + (size_t)Bq * Nq * Fq;
    float* last_m = last_c + (size_t)Bq * Nq * Fq;

    float *pYX, *pY1, *pY2;
    __nv_bfloat16 *pxth, *pxtl, *pSth, *pStl, *phth, *phtl;
    cudaGetSymbolAddress((void**)&pYX,  g_YX);
    cudaGetSymbolAddress((void**)&pY1,  g_Y1);
    cudaGetSymbolAddress((void**)&pY2,  g_Y2);
    cudaGetSymbolAddress((void**)&pxth, g_xth);
    cudaGetSymbolAddress((void**)&pxtl, g_xtl);
    cudaGetSymbolAddress((void**)&pSth, g_Sth);
    cudaGetSymbolAddress((void**)&pStl, g_Stl);
    cudaGetSymbolAddress((void**)&phth, g_hth);
    cudaGetSymbolAddress((void**)&phtl, g_htl);

    const int G1_SMEM = (16384 + 512) * 4;
    const int G2_SMEM = (12288 + 384) * 4;
    const int GEMM64_SMEM = 3 * (2 * 128 * 80 + 2 * 64 * 80);  // 92160
    const int GEMM32_SMEM = 3 * (2 * 128 * 80 + 2 * 32 * 80);  // 76800
    cudaFuncSetAttribute(gates1_kernel, cudaFuncAttributeMaxDynamicSharedMemorySize, G1_SMEM);
    cudaFuncSetAttribute(gates2_kernel, cudaFuncAttributeMaxDynamicSharedMemorySize, G2_SMEM);
    cudaFuncSetAttribute(adj_gemm_mma<64>, cudaFuncAttributeMaxDynamicSharedMemorySize, GEMM64_SMEM);
    cudaFuncSetAttribute(adj_gemm_mma<32>, cudaFuncAttributeMaxDynamicSharedMemorySize, GEMM32_SMEM);

    convert_adj<<<(Bq * Nq * Nq / 4) / 256, 256>>>(adj);
    init_state<<<(Bq * 2 * Fq * Nq + 255) / 256, 256>>>();
    trans_split_x<<<dim3(Nq / 64, 1, Bq * Tq), 256>>>(x, pxth, pxtl);

    // Precompute adj @ x: 24 slabs of BN=64 (t-pairs), full-K, adiv=6
    adj_gemm_mma<64><<<dim3(Nq / 128, 1, Bq * Tq / 2), 256, GEMM64_SMEM>>>(
        pxth, pxtl, (long long)64 * Nq, 6,
        pYX, (long long)Nq * 64, 32, (long long)Nq * 32, 0LL, Nq / 32);

    const long long PS1 = (long long)Bq * Nq * 64;
    const long long PS2 = (long long)Bq * Nq * 32;
    for (int t = 0; t < Tq; t++) {
        // Y1 = adj @ [h|m]^T   (split-K=4, 32 chunks each)
        adj_gemm_mma<64><<<dim3(Nq / 128, 4, Bq), 256, GEMM64_SMEM>>>(
            pSth, pStl, (long long)64 * Nq, 1, pY1, (long long)Nq * 64,
            64, 32LL, PS1, Nq / 128);
        gates1_kernel<<<512, 256, G1_SMEM>>>(W, bias, t, last_c);
        // Y2 = adj @ h_mid^T   (split-K=4)
        adj_gemm_mma<32><<<dim3(Nq / 128, 4, Bq), 256, GEMM32_SMEM>>>(
            phth, phtl, (long long)32 * Nq, 1, pY2, (long long)Nq * 32,
            32, 32LL, PS2, Nq / 128);
        gates2_kernel<<<512, 256, G2_SMEM>>>(W + 8 * (Fq * 2 * Fq), bias + 8 * (2 * Fq),
                                             t, hidden, last_h, last_m);
    }
}

// round 7
// speedup vs baseline: 1.6867x; 1.4656x over previous
#include <cuda_runtime.h>
#include <cuda_bf16.h>
#include <cstdint>

#define Bq 4
#define Tq 12
#define Nq 4096
#define Fq 32

// ---------------------------------------------------------------------------
// PTX helpers — Ampere-era only (compute_103-safe: tcgen05 rejected by ptxas
// at the harness's compute_103 virtual arch; s8 IMMA measured slow in R5;
// term-major MMA ordering measured slow in R6)
// ---------------------------------------------------------------------------
__device__ __forceinline__ uint32_t smem_to_u32(const void* p) {
    uint32_t a;
    asm("{ .reg .u64 t; cvta.to.shared.u64 t, %1; cvt.u32.u64 %0, t; }" : "=r"(a) : "l"(p));
    return a;
}

#define CP_ASYNC16(dst, src) \
    asm volatile("cp.async.cg.shared.global [%0], [%1], 16;" :: "r"(dst), "l"(src) : "memory")
#define CP_COMMIT() asm volatile("cp.async.commit_group;" ::: "memory")
#define CP_WAIT0()  asm volatile("cp.async.wait_group 0;" ::: "memory")

__device__ __forceinline__ void ldsm4(uint32_t addr, uint32_t* r) {
    asm volatile("ldmatrix.sync.aligned.m8n8.x4.shared.b16 {%0,%1,%2,%3}, [%4];"
                 : "=r"(r[0]), "=r"(r[1]), "=r"(r[2]), "=r"(r[3]) : "r"(addr));
}
__device__ __forceinline__ void mma16816(float* d, const uint32_t* a, uint32_t b0, uint32_t b1) {
    asm volatile("mma.sync.aligned.m16n8k16.row.col.f32.bf16.bf16.f32 "
                 "{%0,%1,%2,%3},{%4,%5,%6,%7},{%8,%9},{%0,%1,%2,%3};"
                 : "+f"(d[0]), "+f"(d[1]), "+f"(d[2]), "+f"(d[3])
                 : "r"(a[0]), "r"(a[1]), "r"(a[2]), "r"(a[3]), "r"(b0), "r"(b1));
}

// ---------------------------------------------------------------------------
// Device scratch
// ---------------------------------------------------------------------------
__device__ __align__(128) __nv_bfloat16 g_Ahi[(size_t)Bq * Nq * Nq];
__device__ __align__(128) __nv_bfloat16 g_Alo[(size_t)Bq * Nq * Nq];
__device__ __align__(128) __nv_bfloat16 g_xth[(size_t)Bq * Tq * Fq * Nq];  // [b][t*32+f][n]
__device__ __align__(128) __nv_bfloat16 g_xtl[(size_t)Bq * Tq * Fq * Nq];
__device__ __align__(128) __nv_bfloat16 g_Sth[(size_t)Bq * 2 * Fq * Nq];   // [b][64][n]  (h|m)
__device__ __align__(128) __nv_bfloat16 g_Stl[(size_t)Bq * 2 * Fq * Nq];
__device__ __align__(128) __nv_bfloat16 g_hth[(size_t)Bq * Fq * Nq];       // [b][32][n]  (h_mid)
__device__ __align__(128) __nv_bfloat16 g_htl[(size_t)Bq * Fq * Nq];

__device__ __align__(128) float g_YX[(size_t)Bq * Tq * Nq * Fq];
__device__ __align__(128) float g_Y1[2 * (size_t)Bq * Nq * 2 * Fq];  // split-K=2 partials
__device__ __align__(128) float g_Y2[2 * (size_t)Bq * Nq * Fq];
__device__ __align__(128) float g_m [(size_t)Bq * Nq * Fq];
__device__ __align__(128) float g_c [(size_t)Bq * Nq * Fq];

__device__ __forceinline__ float sigf(float x) { return 1.0f / (1.0f + __expf(-x)); }

// ---------------------------------------------------------------------------
// adj -> bf16 hi/lo split
// ---------------------------------------------------------------------------
__global__ __launch_bounds__(256) void convert_adj(const float* __restrict__ adj) {
    size_t i = (size_t)blockIdx.x * 256 + threadIdx.x;
    float4 v = ((const float4*)adj)[i];
    __nv_bfloat16 h0 = __float2bfloat16(v.x), h1 = __float2bfloat16(v.y);
    __nv_bfloat16 h2 = __float2bfloat16(v.z), h3 = __float2bfloat16(v.w);
    __nv_bfloat16 l0 = __float2bfloat16(v.x - __bfloat162float(h0));
    __nv_bfloat16 l1 = __float2bfloat16(v.y - __bfloat162float(h1));
    __nv_bfloat16 l2 = __float2bfloat16(v.z - __bfloat162float(h2));
    __nv_bfloat16 l3 = __float2bfloat16(v.w - __bfloat162float(h3));
    __nv_bfloat162 hp0 = {h0, h1}, hp1 = {h2, h3}, lp0 = {l0, l1}, lp1 = {l2, l3};
    uint2 hw, lw;
    hw.x = *(uint32_t*)&hp0; hw.y = *(uint32_t*)&hp1;
    lw.x = *(uint32_t*)&lp0; lw.y = *(uint32_t*)&lp1;
    ((uint2*)g_Ahi)[i] = hw;
    ((uint2*)g_Alo)[i] = lw;
}

__global__ void init_state() {
    int i = blockIdx.x * blockDim.x + threadIdx.x;
    if (i < Bq * Nq * Fq) { g_m[i] = 1.0f; g_c[i] = 1.0f; }
    if (i < Bq * 2 * Fq * Nq) {
        g_Sth[i] = __float2bfloat16(1.0f);
        g_Stl[i] = __float2bfloat16(0.0f);
    }
}

// ---------------------------------------------------------------------------
// transpose + bf16 split for x: [z][4096][32] fp32 -> [z][32][4096] bf16 hi/lo
// ---------------------------------------------------------------------------
__global__ __launch_bounds__(256) void trans_split_x(const float* __restrict__ V,
                                                     __nv_bfloat16* __restrict__ Thi,
                                                     __nv_bfloat16* __restrict__ Tlo) {
    __shared__ float tile[64][33];
    const int z = blockIdx.z;
    const int n0 = blockIdx.x * 64;
    const float* v = V + (size_t)z * Nq * 32 + (size_t)n0 * 32;
    const int tid = threadIdx.x;
#pragma unroll
    for (int idx = tid; idx < 64 * 32; idx += 256)
        tile[idx >> 5][idx & 31] = v[idx];
    __syncthreads();
    __nv_bfloat16* th = Thi + (size_t)z * 32 * Nq;
    __nv_bfloat16* tl = Tlo + (size_t)z * 32 * Nq;
#pragma unroll
    for (int idx = tid; idx < 64 * 32; idx += 256) {
        int f = idx >> 6, j = idx & 63;
        float val = tile[j][f];
        __nv_bfloat16 hi = __float2bfloat16(val);
        __nv_bfloat16 lo = __float2bfloat16(val - __bfloat162float(hi));
        th[(size_t)f * Nq + n0 + j] = hi;
        tl[(size_t)f * Nq + n0 + j] = lo;
    }
}

// ---------------------------------------------------------------------------
// split-bf16 mma.sync GEMM with split-K:
//   Y[part=blockIdx.y][z] = adj[z/adiv][kseg] @ V[z][kseg]
// D = Ahi*Bhi + Ahi*Blo + Alo*Bhi, fp32 register accumulators.
// BM=128, BK=32, 8 warps 4(m) x 2(n).
// 2-stage cp.async pipeline, single barrier per chunk, 3 CTAs/SM:
//   issue(c+1) runs after the sync that proves compute(c-1) finished in all
//   warps, and writes buf[(c+1)&1] == buf[(c-1)&1] -> safe.
// MMA ordering: per-(mf,nf) interleaved hh,hl,lh (R4-proven; term-major
// regressed in R6).
// ---------------------------------------------------------------------------
template <int BN>
__global__ __launch_bounds__(256, 3) void adj_gemm_mma(
    const __nv_bfloat16* __restrict__ Bhi_g, const __nv_bfloat16* __restrict__ Blo_g,
    long long bZ, int adiv, float* __restrict__ Y, long long yZ,
    int rstride, long long gstride, long long partStride, int nch) {
    constexpr int RB = 80;                 // 64B data + 16B pad
    constexpr int A_BYTES = 128 * RB;
    constexpr int B_BYTES = BN * RB;
    constexpr int OFF_AH = 0, OFF_AL = A_BYTES;
    constexpr int OFF_BH = 2 * A_BYTES, OFF_BL = 2 * A_BYTES + B_BYTES;
    constexpr int STAGE = 2 * A_BYTES + 2 * B_BYTES;
    constexpr int WN = BN / 2;
    constexpr int NF = WN / 8;
    constexpr int NB = (NF + 1) / 2;

    extern __shared__ char smc[];
    const uint32_t sbase = smem_to_u32(smc);
    const int tid = threadIdx.x;
    const int wid = tid >> 5, lane = tid & 31;
    const int wm = wid & 3, wn = wid >> 2;
    const int z = blockIdx.z;
    const int m0 = blockIdx.x * 128;
    const int kbase = blockIdx.y * nch * 32;

    const __nv_bfloat16* gAh = g_Ahi + (size_t)(z / adiv) * Nq * Nq + (size_t)m0 * Nq + kbase;
    const __nv_bfloat16* gAl = g_Alo + (size_t)(z / adiv) * Nq * Nq + (size_t)m0 * Nq + kbase;
    const __nv_bfloat16* gBh = Bhi_g + (size_t)z * bZ + kbase;
    const __nv_bfloat16* gBl = Blo_g + (size_t)z * bZ + kbase;

    const int arow = tid >> 2;
    const int acol = tid & 3;
    const int brow = tid >> 2;
    const bool bact = (BN == 64) || (tid < 128);

    float acc[2][NF][4];
#pragma unroll
    for (int mf = 0; mf < 2; mf++)
#pragma unroll
        for (int nf = 0; nf < NF; nf++)
#pragma unroll
            for (int q = 0; q < 4; q++) acc[mf][nf][q] = 0.0f;

    auto issue = [&](int c) {
        const uint32_t st = sbase + (uint32_t)(c & 1) * STAGE;
        const int k0 = c * 32;
#pragma unroll
        for (int rep = 0; rep < 2; rep++) {
            int r = rep * 64 + arow;
            uint32_t d = st + r * RB + acol * 16;
            CP_ASYNC16(d + OFF_AH, gAh + (size_t)r * Nq + k0 + acol * 8);
            CP_ASYNC16(d + OFF_AL, gAl + (size_t)r * Nq + k0 + acol * 8);
        }
        if (bact) {
            uint32_t d = st + brow * RB + acol * 16;
            CP_ASYNC16(d + OFF_BH, gBh + (size_t)brow * Nq + k0 + acol * 8);
            CP_ASYNC16(d + OFF_BL, gBl + (size_t)brow * Nq + k0 + acol * 8);
        }
    };

    issue(0); CP_COMMIT();

    const int a_r = (lane & 15);
    const int a_k = (lane >> 4) * 16;
    const int b_r = ((lane >> 4) << 3) + (lane & 7);
    const int b_k = ((lane >> 3) & 1) * 16;

#pragma unroll 1
    for (int c = 0; c < nch; c++) {
        CP_WAIT0();          // group c arrived (only outstanding group)
        __syncthreads();     // all warps done compute(c-1): buf[(c+1)&1] free
        if (c + 1 < nch) { issue(c + 1); CP_COMMIT(); }

        const uint32_t st = sbase + (uint32_t)(c & 1) * STAGE;
#pragma unroll
        for (int ks = 0; ks < 2; ks++) {
            uint32_t ah[2][4], al[2][4];
#pragma unroll
            for (int mf = 0; mf < 2; mf++) {
                uint32_t addr = st + (wm * 32 + mf * 16 + a_r) * RB + ks * 32 + a_k;
                ldsm4(addr + OFF_AH, ah[mf]);
                ldsm4(addr + OFF_AL, al[mf]);
            }
            uint32_t bh[NB][4], bl[NB][4];
#pragma unroll
            for (int nb = 0; nb < NB; nb++) {
                uint32_t addr = st + (wn * WN + nb * 16 + b_r) * RB + ks * 32 + b_k;
                ldsm4(addr + OFF_BH, bh[nb]);
                ldsm4(addr + OFF_BL, bl[nb]);
            }
#pragma unroll
            for (int mf = 0; mf < 2; mf++)
#pragma unroll
                for (int nf = 0; nf < NF; nf++) {
                    const int nb = nf >> 1, pr = (nf & 1) * 2;
                    mma16816(acc[mf][nf], ah[mf], bh[nb][pr], bh[nb][pr + 1]);
                    mma16816(acc[mf][nf], ah[mf], bl[nb][pr], bl[nb][pr + 1]);
                    mma16816(acc[mf][nf], al[mf], bh[nb][pr], bh[nb][pr + 1]);
                }
        }
    }

    float* yb = Y + (size_t)blockIdx.y * partStride + (size_t)z * yZ;
#pragma unroll
    for (int mf = 0; mf < 2; mf++)
#pragma unroll
        for (int nf = 0; nf < NF; nf++) {
            int r = m0 + wm * 32 + mf * 16 + (lane >> 2);
            int cj = wn * WN + nf * 8 + (lane & 3) * 2;
            size_t off = (size_t)(cj >> 5) * gstride + (cj & 31);
            float* o0 = yb + (size_t)r * rstride + off;
            float* o1 = yb + (size_t)(r + 8) * rstride + off;
            *(float2*)o0 = make_float2(acc[mf][nf][0], acc[mf][nf][1]);
            *(float2*)o1 = make_float2(acc[mf][nf][2], acc[mf][nf][3]);
        }
}

// ---------------------------------------------------------------------------
// gates1: LSTM gates 0..7; sums 2 split-K partials; writes h_mid transposed
// as bf16 hi/lo.
// ---------------------------------------------------------------------------
__global__ __launch_bounds__(256) void gates1_kernel(const float* __restrict__ W,
                                                     const float* __restrict__ bias,
                                                     int t, float* __restrict__ last_c) {
    extern __shared__ float sm[];
    float4* Wp = (float4*)sm;
    float4* bp = (float4*)(sm + 16384);
    const long long PS1 = (long long)Bq * Nq * 64;

    const int tid = threadIdx.x;
    for (int idx = tid; idx < 4096; idx += 256) {
        int l = idx & 31, p = (idx >> 5) & 3, k = idx >> 7;
        const float* W0 = W + (2 * p) * (Fq * 2 * Fq) + k * (2 * Fq);
        const float* W1 = W + (2 * p + 1) * (Fq * 2 * Fq) + k * (2 * Fq);
        Wp[idx] = make_float4(W0[l], W0[l + 32], W1[l], W1[l + 32]);
    }
    if (tid < 128) {
        int l = tid & 31, p = tid >> 5;
        bp[p * 32 + l] = make_float4(bias[(2 * p) * 64 + l], bias[(2 * p) * 64 + 32 + l],
                                     bias[(2 * p + 1) * 64 + l], bias[(2 * p + 1) * 64 + 32 + l]);
    }
    __syncthreads();

    const int w = tid >> 5, l = tid & 31;
    const int nrows = Bq * Nq;
    for (int row = blockIdx.x * 8 + w; row < nrows; row += gridDim.x * 8) {
        int b = row >> 12, n = row & (Nq - 1);
        float yx = g_YX[(((size_t)b * Tq + t) * Nq + n) * Fq + l];
        float yh = g_Y1[(size_t)row * 64 + l] + g_Y1[PS1 + (size_t)row * 64 + l];

        float acc[4][4];
#pragma unroll
        for (int p = 0; p < 4; p++)
#pragma unroll
            for (int q = 0; q < 4; q++) acc[p][q] = 0.0f;

#pragma unroll
        for (int k = 0; k < 32; k++) {
            float ykx = __shfl_sync(0xffffffffu, yx, k);
            float ykh = __shfl_sync(0xffffffffu, yh, k);
#pragma unroll
            for (int p = 0; p < 4; p++) {
                float4 wv = Wp[k * 128 + p * 32 + l];
                acc[p][0] = fmaf(ykx, wv.x, acc[p][0]);
                acc[p][1] = fmaf(ykx, wv.y, acc[p][1]);
                acc[p][2] = fmaf(ykh, wv.z, acc[p][2]);
                acc[p][3] = fmaf(ykh, wv.w, acc[p][3]);
            }
        }

        float s[4];
#pragma unroll
        for (int p = 0; p < 4; p++) {
            float4 bb = bp[p * 32 + l];
            float gx = (acc[p][0] + bb.x) * sigf(acc[p][1] + bb.y);
            float gh = (acc[p][2] + bb.z) * sigf(acc[p][3] + bb.w);
            s[p] = gx + gh;
        }
        float f  = sigf(s[0]);
        float ig = sigf(s[1]);
        float o  = sigf(s[3]);
        size_t ci = (size_t)row * Fq + l;
        float cn = f * g_c[ci] + ig * tanhf(s[2]);
        g_c[ci] = cn;
        float hm = o * tanhf(cn);
        size_t ti = ((size_t)b * Fq + l) * Nq + n;
        __nv_bfloat16 hi = __float2bfloat16(hm);
        g_hth[ti] = hi;
        g_htl[ti] = __float2bfloat16(hm - __bfloat162float(hi));
        if (t == Tq - 1) last_c[ci] = cn;
    }
}

// ---------------------------------------------------------------------------
// gates2: memory gates 8..13; sums 2 split-K partials; writes new [h|m]
// transposed bf16 hi/lo.
// ---------------------------------------------------------------------------
__global__ __launch_bounds__(256) void gates2_kernel(const float* __restrict__ W8,
                                                     const float* __restrict__ bias8,
                                                     int t, float* __restrict__ hidden,
                                                     float* __restrict__ last_h,
                                                     float* __restrict__ last_m) {
    extern __shared__ float sm[];
    float4* Wp = (float4*)sm;
    float4* bp = (float4*)(sm + 12288);
    const long long PS1 = (long long)Bq * Nq * 64;
    const long long PS2 = (long long)Bq * Nq * 32;

    const int tid = threadIdx.x;
    for (int idx = tid; idx < 3072; idx += 256) {
        int k = idx / 96, r = idx % 96, p = r >> 5, l = r & 31;
        const float* W0 = W8 + (2 * p) * (Fq * 2 * Fq) + k * (2 * Fq);
        const float* W1 = W8 + (2 * p + 1) * (Fq * 2 * Fq) + k * (2 * Fq);
        Wp[idx] = make_float4(W0[l], W0[l + 32], W1[l], W1[l + 32]);
    }
    if (tid < 96) {
        int p = tid >> 5, l = tid & 31;
        bp[tid] = make_float4(bias8[(2 * p) * 64 + l], bias8[(2 * p) * 64 + 32 + l],
                              bias8[(2 * p + 1) * 64 + l], bias8[(2 * p + 1) * 64 + 32 + l]);
    }
    __syncthreads();

    const int w = tid >> 5, l = tid & 31;
    const int nrows = Bq * Nq;
    for (int row = blockIdx.x * 8 + w; row < nrows; row += gridDim.x * 8) {
        int b = row >> 12, n = row & (Nq - 1);
        float y2 = g_Y2[(size_t)row * 32 + l] + g_Y2[PS2 + (size_t)row * 32 + l];
        float ym = g_Y1[(size_t)row * 64 + 32 + l] + g_Y1[PS1 + (size_t)row * 64 + 32 + l];

        float acc[3][4];
#pragma unroll
        for (int p = 0; p < 3; p++)
#pragma unroll
            for (int q = 0; q < 4; q++) acc[p][q] = 0.0f;

#pragma unroll
        for (int k = 0; k < 32; k++) {
            float yk2 = __shfl_sync(0xffffffffu, y2, k);
            float ykm = __shfl_sync(0xffffffffu, ym, k);
#pragma unroll
            for (int p = 0; p < 3; p++) {
                float4 wv = Wp[k * 96 + p * 32 + l];
                acc[p][0] = fmaf(yk2, wv.x, acc[p][0]);
                acc[p][1] = fmaf(yk2, wv.y, acc[p][1]);
                acc[p][2] = fmaf(ykm, wv.z, acc[p][2]);
                acc[p][3] = fmaf(ykm, wv.w, acc[p][3]);
            }
        }

        float s[3];
#pragma unroll
        for (int p = 0; p < 3; p++) {
            float4 bb = bp[p * 32 + l];
            float gx = (acc[p][0] + bb.x) * sigf(acc[p][1] + bb.y);
            float gh = (acc[p][2] + bb.z) * sigf(acc[p][3] + bb.w);
            s[p] = gx + gh;
        }
        float i2 = sigf(s[0]);
        float gg = sigf(s[1]);
        float o2 = sigf(s[2]);
        size_t ci = (size_t)row * Fq + l;
        float mo = g_m[ci];
        float mn = i2 * mo + (1.0f - i2) * gg;
        float hn = mn * o2;
        g_m[ci] = mn;
        size_t th = ((size_t)b * 64 + l) * Nq + n;
        size_t tm = ((size_t)b * 64 + 32 + l) * Nq + n;
        __nv_bfloat16 hh = __float2bfloat16(hn);
        __nv_bfloat16 mh = __float2bfloat16(mn);
        g_Sth[th] = hh;
        g_Stl[th] = __float2bfloat16(hn - __bfloat162float(hh));
        g_Sth[tm] = mh;
        g_Stl[tm] = __float2bfloat16(mn - __bfloat162float(mh));
        hidden[(((size_t)b * Tq + t) * Nq + n) * Fq + l] = hn;
        if (t == Tq - 1) {
            last_h[ci] = hn;
            last_m[ci] = mn;
        }
    }
}

// ---------------------------------------------------------------------------
// kernel_launch
// ---------------------------------------------------------------------------
extern "C" void kernel_launch(void* const* d_in, const int* in_sizes, int n_in,
                              void* d_out, int out_size) {
    (void)in_sizes; (void)n_in; (void)out_size;
    const float* x    = (const float*)d_in[0];
    const float* adj  = (const float*)d_in[1];
    const float* W    = (const float*)d_in[2];
    const float* bias = (const float*)d_in[3];

    float* hidden = (float*)d_out;
    float* last_h = hidden + (size_t)Bq * Tq * Nq * Fq;
    float* last_c = last_h + (size_t)Bq * Nq * Fq;
    float* last_m = last_c + (size_t)Bq * Nq * Fq;

    float *pYX, *pY1, *pY2;
    __nv_bfloat16 *pxth, *pxtl, *pSth, *pStl, *phth, *phtl;
    cudaGetSymbolAddress((void**)&pYX,  g_YX);
    cudaGetSymbolAddress((void**)&pY1,  g_Y1);
    cudaGetSymbolAddress((void**)&pY2,  g_Y2);
    cudaGetSymbolAddress((void**)&pxth, g_xth);
    cudaGetSymbolAddress((void**)&pxtl, g_xtl);
    cudaGetSymbolAddress((void**)&pSth, g_Sth);
    cudaGetSymbolAddress((void**)&pStl, g_Stl);
    cudaGetSymbolAddress((void**)&phth, g_hth);
    cudaGetSymbolAddress((void**)&phtl, g_htl);

    const int G1_SMEM = (16384 + 512) * 4;
    const int G2_SMEM = (12288 + 384) * 4;
    const int GEMM64_SMEM = 2 * (2 * 128 * 80 + 2 * 64 * 80);  // 61440
    const int GEMM32_SMEM = 2 * (2 * 128 * 80 + 2 * 32 * 80);  // 51200
    cudaFuncSetAttribute(gates1_kernel, cudaFuncAttributeMaxDynamicSharedMemorySize, G1_SMEM);
    cudaFuncSetAttribute(gates2_kernel, cudaFuncAttributeMaxDynamicSharedMemorySize, G2_SMEM);
    cudaFuncSetAttribute(adj_gemm_mma<64>, cudaFuncAttributeMaxDynamicSharedMemorySize, GEMM64_SMEM);
    cudaFuncSetAttribute(adj_gemm_mma<32>, cudaFuncAttributeMaxDynamicSharedMemorySize, GEMM32_SMEM);

    convert_adj<<<(Bq * Nq * Nq / 4) / 256, 256>>>(adj);
    init_state<<<(Bq * 2 * Fq * Nq + 255) / 256, 256>>>();
    trans_split_x<<<dim3(Nq / 64, 1, Bq * Tq), 256>>>(x, pxth, pxtl);

    // Precompute adj @ x: 24 slabs of BN=64 (t-pairs), full-K, adiv=6
    adj_gemm_mma<64><<<dim3(Nq / 128, 1, Bq * Tq / 2), 256, GEMM64_SMEM>>>(
        pxth, pxtl, (long long)64 * Nq, 6,
        pYX, (long long)Nq * 64, 32, (long long)Nq * 32, 0LL, Nq / 32);

    const long long PS1 = (long long)Bq * Nq * 64;
    const long long PS2 = (long long)Bq * Nq * 32;
    for (int t = 0; t < Tq; t++) {
        // Y1 = adj @ [h|m]^T   (split-K=2, 64 chunks each)
        adj_gemm_mma<64><<<dim3(Nq / 128, 2, Bq), 256, GEMM64_SMEM>>>(
            pSth, pStl, (long long)64 * Nq, 1, pY1, (long long)Nq * 64,
            64, 32LL, PS1, Nq / 64);
        gates1_kernel<<<512, 256, G1_SMEM>>>(W, bias, t, last_c);
        // Y2 = adj @ h_mid^T   (split-K=2)
        adj_gemm_mma<32><<<dim3(Nq / 128, 2, Bq), 256, GEMM32_SMEM>>>(
            phth, phtl, (long long)32 * Nq, 1, pY2, (long long)Nq * 32,
            32, 32LL, PS2, Nq / 64);
        gates2_kernel<<<512, 256, G2_SMEM>>>(W + 8 * (Fq * 2 * Fq), bias + 8 * (2 * Fq),
                                             t, hidden, last_h, last_m);
    }
}

// round 8
// speedup vs baseline: 1.7885x; 1.0603x over previous
#include <cuda_runtime.h>
#include <cuda_bf16.h>
#include <cstdint>

#define Bq 4
#define Tq 12
#define Nq 4096
#define Fq 32

// ---------------------------------------------------------------------------
// PTX helpers — Ampere-era only (compute_103-safe: tcgen05 rejected by ptxas
// at the harness's compute_103 virtual arch; s8 IMMA measured slow in R5;
// term-major MMA ordering measured slow in R6; 2-stage/3-CTA neutral in R7)
// ---------------------------------------------------------------------------
__device__ __forceinline__ uint32_t smem_to_u32(const void* p) {
    uint32_t a;
    asm("{ .reg .u64 t; cvta.to.shared.u64 t, %1; cvt.u32.u64 %0, t; }" : "=r"(a) : "l"(p));
    return a;
}

#define CP_ASYNC16(dst, src) \
    asm volatile("cp.async.cg.shared.global [%0], [%1], 16;" :: "r"(dst), "l"(src) : "memory")
#define CP_COMMIT() asm volatile("cp.async.commit_group;" ::: "memory")
#define CP_WAIT0()  asm volatile("cp.async.wait_group 0;" ::: "memory")
#define CP_WAIT1()  asm volatile("cp.async.wait_group 1;" ::: "memory")

__device__ __forceinline__ void ldsm4(uint32_t addr, uint32_t* r) {
    asm volatile("ldmatrix.sync.aligned.m8n8.x4.shared.b16 {%0,%1,%2,%3}, [%4];"
                 : "=r"(r[0]), "=r"(r[1]), "=r"(r[2]), "=r"(r[3]) : "r"(addr));
}
__device__ __forceinline__ void mma16816(float* d, const uint32_t* a, uint32_t b0, uint32_t b1) {
    asm volatile("mma.sync.aligned.m16n8k16.row.col.f32.bf16.bf16.f32 "
                 "{%0,%1,%2,%3},{%4,%5,%6,%7},{%8,%9},{%0,%1,%2,%3};"
                 : "+f"(d[0]), "+f"(d[1]), "+f"(d[2]), "+f"(d[3])
                 : "r"(a[0]), "r"(a[1]), "r"(a[2]), "r"(a[3]), "r"(b0), "r"(b1));
}

// ---------------------------------------------------------------------------
// Device scratch
// ---------------------------------------------------------------------------
__device__ __align__(128) __nv_bfloat16 g_Ahi[(size_t)Bq * Nq * Nq];
__device__ __align__(128) __nv_bfloat16 g_Alo[(size_t)Bq * Nq * Nq];
__device__ __align__(128) __nv_bfloat16 g_xth[(size_t)Bq * Tq * Fq * Nq];  // [b][t*32+f][n]
__device__ __align__(128) __nv_bfloat16 g_xtl[(size_t)Bq * Tq * Fq * Nq];
__device__ __align__(128) __nv_bfloat16 g_Sth[(size_t)Bq * 2 * Fq * Nq];   // [b][64][n]  (h|m)
__device__ __align__(128) __nv_bfloat16 g_Stl[(size_t)Bq * 2 * Fq * Nq];
__device__ __align__(128) __nv_bfloat16 g_hth[(size_t)Bq * Fq * Nq];       // [b][32][n]  (h_mid)
__device__ __align__(128) __nv_bfloat16 g_htl[(size_t)Bq * Fq * Nq];

__device__ __align__(128) float g_YX[(size_t)Bq * Tq * Nq * Fq];
__device__ __align__(128) float g_Y1[2 * (size_t)Bq * Nq * 2 * Fq];  // split-K=2 partials
__device__ __align__(128) float g_Y2[2 * (size_t)Bq * Nq * Fq];
__device__ __align__(128) float g_m [(size_t)Bq * Nq * Fq];
__device__ __align__(128) float g_c [(size_t)Bq * Nq * Fq];

__device__ __forceinline__ float sigf(float x) { return 1.0f / (1.0f + __expf(-x)); }

// ---------------------------------------------------------------------------
// adj -> bf16 hi/lo split
// ---------------------------------------------------------------------------
__global__ __launch_bounds__(256) void convert_adj(const float* __restrict__ adj) {
    size_t i = (size_t)blockIdx.x * 256 + threadIdx.x;
    float4 v = ((const float4*)adj)[i];
    __nv_bfloat16 h0 = __float2bfloat16(v.x), h1 = __float2bfloat16(v.y);
    __nv_bfloat16 h2 = __float2bfloat16(v.z), h3 = __float2bfloat16(v.w);
    __nv_bfloat16 l0 = __float2bfloat16(v.x - __bfloat162float(h0));
    __nv_bfloat16 l1 = __float2bfloat16(v.y - __bfloat162float(h1));
    __nv_bfloat16 l2 = __float2bfloat16(v.z - __bfloat162float(h2));
    __nv_bfloat16 l3 = __float2bfloat16(v.w - __bfloat162float(h3));
    __nv_bfloat162 hp0 = {h0, h1}, hp1 = {h2, h3}, lp0 = {l0, l1}, lp1 = {l2, l3};
    uint2 hw, lw;
    hw.x = *(uint32_t*)&hp0; hw.y = *(uint32_t*)&hp1;
    lw.x = *(uint32_t*)&lp0; lw.y = *(uint32_t*)&lp1;
    ((uint2*)g_Ahi)[i] = hw;
    ((uint2*)g_Alo)[i] = lw;
}

__global__ void init_state() {
    int i = blockIdx.x * blockDim.x + threadIdx.x;
    if (i < Bq * Nq * Fq) { g_m[i] = 1.0f; g_c[i] = 1.0f; }
    if (i < Bq * 2 * Fq * Nq) {
        g_Sth[i] = __float2bfloat16(1.0f);
        g_Stl[i] = __float2bfloat16(0.0f);
    }
}

// ---------------------------------------------------------------------------
// transpose + bf16 split for x: [z][4096][32] fp32 -> [z][32][4096] bf16 hi/lo
// ---------------------------------------------------------------------------
__global__ __launch_bounds__(256) void trans_split_x(const float* __restrict__ V,
                                                     __nv_bfloat16* __restrict__ Thi,
                                                     __nv_bfloat16* __restrict__ Tlo) {
    __shared__ float tile[64][33];
    const int z = blockIdx.z;
    const int n0 = blockIdx.x * 64;
    const float* v = V + (size_t)z * Nq * 32 + (size_t)n0 * 32;
    const int tid = threadIdx.x;
#pragma unroll
    for (int idx = tid; idx < 64 * 32; idx += 256)
        tile[idx >> 5][idx & 31] = v[idx];
    __syncthreads();
    __nv_bfloat16* th = Thi + (size_t)z * 32 * Nq;
    __nv_bfloat16* tl = Tlo + (size_t)z * 32 * Nq;
#pragma unroll
    for (int idx = tid; idx < 64 * 32; idx += 256) {
        int f = idx >> 6, j = idx & 63;
        float val = tile[j][f];
        __nv_bfloat16 hi = __float2bfloat16(val);
        __nv_bfloat16 lo = __float2bfloat16(val - __bfloat162float(hi));
        th[(size_t)f * Nq + n0 + j] = hi;
        tl[(size_t)f * Nq + n0 + j] = lo;
    }
}

// ---------------------------------------------------------------------------
// split-bf16 mma.sync GEMM with split-K (R4-proven config):
//   Y[part=blockIdx.y][z] = adj[z/adiv][kseg] @ V[z][kseg]
// D = Ahi*Bhi + Ahi*Blo + Alo*Bhi, fp32 register accumulators.
// BM=128, BK=32, 8 warps 4(m) x 2(n), 3-stage cp.async, 2 CTAs/SM,
// per-(mf,nf) interleaved MMA ordering.
// ---------------------------------------------------------------------------
template <int BN>
__global__ __launch_bounds__(256, 2) void adj_gemm_mma(
    const __nv_bfloat16* __restrict__ Bhi_g, const __nv_bfloat16* __restrict__ Blo_g,
    long long bZ, int adiv, float* __restrict__ Y, long long yZ,
    int rstride, long long gstride, long long partStride, int nch) {
    constexpr int RB = 80;                 // 64B data + 16B pad
    constexpr int A_BYTES = 128 * RB;
    constexpr int B_BYTES = BN * RB;
    constexpr int OFF_AH = 0, OFF_AL = A_BYTES;
    constexpr int OFF_BH = 2 * A_BYTES, OFF_BL = 2 * A_BYTES + B_BYTES;
    constexpr int STAGE = 2 * A_BYTES + 2 * B_BYTES;
    constexpr int WN = BN / 2;
    constexpr int NF = WN / 8;
    constexpr int NB = (NF + 1) / 2;

    extern __shared__ char smc[];
    const uint32_t sbase = smem_to_u32(smc);
    const int tid = threadIdx.x;
    const int wid = tid >> 5, lane = tid & 31;
    const int wm = wid & 3, wn = wid >> 2;
    const int z = blockIdx.z;
    const int m0 = blockIdx.x * 128;
    const int kbase = blockIdx.y * nch * 32;

    const __nv_bfloat16* gAh = g_Ahi + (size_t)(z / adiv) * Nq * Nq + (size_t)m0 * Nq + kbase;
    const __nv_bfloat16* gAl = g_Alo + (size_t)(z / adiv) * Nq * Nq + (size_t)m0 * Nq + kbase;
    const __nv_bfloat16* gBh = Bhi_g + (size_t)z * bZ + kbase;
    const __nv_bfloat16* gBl = Blo_g + (size_t)z * bZ + kbase;

    const int arow = tid >> 2;
    const int acol = tid & 3;
    const int brow = tid >> 2;
    const bool bact = (BN == 64) || (tid < 128);

    float acc[2][NF][4];
#pragma unroll
    for (int mf = 0; mf < 2; mf++)
#pragma unroll
        for (int nf = 0; nf < NF; nf++)
#pragma unroll
            for (int q = 0; q < 4; q++) acc[mf][nf][q] = 0.0f;

    auto issue = [&](int c) {
        const uint32_t st = sbase + (uint32_t)(c % 3) * STAGE;
        const int k0 = c * 32;
#pragma unroll
        for (int rep = 0; rep < 2; rep++) {
            int r = rep * 64 + arow;
            uint32_t d = st + r * RB + acol * 16;
            CP_ASYNC16(d + OFF_AH, gAh + (size_t)r * Nq + k0 + acol * 8);
            CP_ASYNC16(d + OFF_AL, gAl + (size_t)r * Nq + k0 + acol * 8);
        }
        if (bact) {
            uint32_t d = st + brow * RB + acol * 16;
            CP_ASYNC16(d + OFF_BH, gBh + (size_t)brow * Nq + k0 + acol * 8);
            CP_ASYNC16(d + OFF_BL, gBl + (size_t)brow * Nq + k0 + acol * 8);
        }
    };

    issue(0); CP_COMMIT();
    issue(1); CP_COMMIT();

    const int a_r = (lane & 15);
    const int a_k = (lane >> 4) * 16;
    const int b_r = ((lane >> 4) << 3) + (lane & 7);
    const int b_k = ((lane >> 3) & 1) * 16;

#pragma unroll 1
    for (int c = 0; c < nch; c++) {
        if (c + 1 < nch) { CP_WAIT1(); } else { CP_WAIT0(); }
        __syncthreads();
        if (c + 2 < nch) { issue(c + 2); CP_COMMIT(); }

        const uint32_t st = sbase + (uint32_t)(c % 3) * STAGE;
#pragma unroll
        for (int ks = 0; ks < 2; ks++) {
            uint32_t ah[2][4], al[2][4];
#pragma unroll
            for (int mf = 0; mf < 2; mf++) {
                uint32_t addr = st + (wm * 32 + mf * 16 + a_r) * RB + ks * 32 + a_k;
                ldsm4(addr + OFF_AH, ah[mf]);
                ldsm4(addr + OFF_AL, al[mf]);
            }
            uint32_t bh[NB][4], bl[NB][4];
#pragma unroll
            for (int nb = 0; nb < NB; nb++) {
                uint32_t addr = st + (wn * WN + nb * 16 + b_r) * RB + ks * 32 + b_k;
                ldsm4(addr + OFF_BH, bh[nb]);
                ldsm4(addr + OFF_BL, bl[nb]);
            }
#pragma unroll
            for (int mf = 0; mf < 2; mf++)
#pragma unroll
                for (int nf = 0; nf < NF; nf++) {
                    const int nb = nf >> 1, pr = (nf & 1) * 2;
                    mma16816(acc[mf][nf], ah[mf], bh[nb][pr], bh[nb][pr + 1]);
                    mma16816(acc[mf][nf], ah[mf], bl[nb][pr], bl[nb][pr + 1]);
                    mma16816(acc[mf][nf], al[mf], bh[nb][pr], bh[nb][pr + 1]);
                }
        }
    }

    float* yb = Y + (size_t)blockIdx.y * partStride + (size_t)z * yZ;
#pragma unroll
    for (int mf = 0; mf < 2; mf++)
#pragma unroll
        for (int nf = 0; nf < NF; nf++) {
            int r = m0 + wm * 32 + mf * 16 + (lane >> 2);
            int cj = wn * WN + nf * 8 + (lane & 3) * 2;
            size_t off = (size_t)(cj >> 5) * gstride + (cj & 31);
            float* o0 = yb + (size_t)r * rstride + off;
            float* o1 = yb + (size_t)(r + 8) * rstride + off;
            *(float2*)o0 = make_float2(acc[mf][nf][0], acc[mf][nf][1]);
            *(float2*)o1 = make_float2(acc[mf][nf][2], acc[mf][nf][3]);
        }
}

// ---------------------------------------------------------------------------
// gates1: LSTM gates 0..7; sums 2 split-K partials; writes h_mid transposed
// as bf16 hi/lo.
// ---------------------------------------------------------------------------
__global__ __launch_bounds__(256) void gates1_kernel(const float* __restrict__ W,
                                                     const float* __restrict__ bias,
                                                     int t, float* __restrict__ last_c) {
    extern __shared__ float sm[];
    float4* Wp = (float4*)sm;
    float4* bp = (float4*)(sm + 16384);
    const long long PS1 = (long long)Bq * Nq * 64;

    const int tid = threadIdx.x;
    for (int idx = tid; idx < 4096; idx += 256) {
        int l = idx & 31, p = (idx >> 5) & 3, k = idx >> 7;
        const float* W0 = W + (2 * p) * (Fq * 2 * Fq) + k * (2 * Fq);
        const float* W1 = W + (2 * p + 1) * (Fq * 2 * Fq) + k * (2 * Fq);
        Wp[idx] = make_float4(W0[l], W0[l + 32], W1[l], W1[l + 32]);
    }
    if (tid < 128) {
        int l = tid & 31, p = tid >> 5;
        bp[p * 32 + l] = make_float4(bias[(2 * p) * 64 + l], bias[(2 * p) * 64 + 32 + l],
                                     bias[(2 * p + 1) * 64 + l], bias[(2 * p + 1) * 64 + 32 + l]);
    }
    __syncthreads();

    const int w = tid >> 5, l = tid & 31;
    const int nrows = Bq * Nq;
    for (int row = blockIdx.x * 8 + w; row < nrows; row += gridDim.x * 8) {
        int b = row >> 12, n = row & (Nq - 1);
        float yx = g_YX[(((size_t)b * Tq + t) * Nq + n) * Fq + l];
        float yh = g_Y1[(size_t)row * 64 + l] + g_Y1[PS1 + (size_t)row * 64 + l];

        float acc[4][4];
#pragma unroll
        for (int p = 0; p < 4; p++)
#pragma unroll
            for (int q = 0; q < 4; q++) acc[p][q] = 0.0f;

#pragma unroll
        for (int k = 0; k < 32; k++) {
            float ykx = __shfl_sync(0xffffffffu, yx, k);
            float ykh = __shfl_sync(0xffffffffu, yh, k);
#pragma unroll
            for (int p = 0; p < 4; p++) {
                float4 wv = Wp[k * 128 + p * 32 + l];
                acc[p][0] = fmaf(ykx, wv.x, acc[p][0]);
                acc[p][1] = fmaf(ykx, wv.y, acc[p][1]);
                acc[p][2] = fmaf(ykh, wv.z, acc[p][2]);
                acc[p][3] = fmaf(ykh, wv.w, acc[p][3]);
            }
        }

        float s[4];
#pragma unroll
        for (int p = 0; p < 4; p++) {
            float4 bb = bp[p * 32 + l];
            float gx = (acc[p][0] + bb.x) * sigf(acc[p][1] + bb.y);
            float gh = (acc[p][2] + bb.z) * sigf(acc[p][3] + bb.w);
            s[p] = gx + gh;
        }
        float f  = sigf(s[0]);
        float ig = sigf(s[1]);
        float o  = sigf(s[3]);
        size_t ci = (size_t)row * Fq + l;
        float cn = f * g_c[ci] + ig * tanhf(s[2]);
        g_c[ci] = cn;
        float hm = o * tanhf(cn);
        size_t ti = ((size_t)b * Fq + l) * Nq + n;
        __nv_bfloat16 hi = __float2bfloat16(hm);
        g_hth[ti] = hi;
        g_htl[ti] = __float2bfloat16(hm - __bfloat162float(hi));
        if (t == Tq - 1) last_c[ci] = cn;
    }
}

// ---------------------------------------------------------------------------
// gates2: memory gates 8..13; sums 2 split-K partials; writes new [h|m]
// transposed bf16 hi/lo.
// ---------------------------------------------------------------------------
__global__ __launch_bounds__(256) void gates2_kernel(const float* __restrict__ W8,
                                                     const float* __restrict__ bias8,
                                                     int t, float* __restrict__ hidden,
                                                     float* __restrict__ last_h,
                                                     float* __restrict__ last_m) {
    extern __shared__ float sm[];
    float4* Wp = (float4*)sm;
    float4* bp = (float4*)(sm + 12288);
    const long long PS1 = (long long)Bq * Nq * 64;
    const long long PS2 = (long long)Bq * Nq * 32;

    const int tid = threadIdx.x;
    for (int idx = tid; idx < 3072; idx += 256) {
        int k = idx / 96, r = idx % 96, p = r >> 5, l = r & 31;
        const float* W0 = W8 + (2 * p) * (Fq * 2 * Fq) + k * (2 * Fq);
        const float* W1 = W8 + (2 * p + 1) * (Fq * 2 * Fq) + k * (2 * Fq);
        Wp[idx] = make_float4(W0[l], W0[l + 32], W1[l], W1[l + 32]);
    }
    if (tid < 96) {
        int p = tid >> 5, l = tid & 31;
        bp[tid] = make_float4(bias8[(2 * p) * 64 + l], bias8[(2 * p) * 64 + 32 + l],
                              bias8[(2 * p + 1) * 64 + l], bias8[(2 * p + 1) * 64 + 32 + l]);
    }
    __syncthreads();

    const int w = tid >> 5, l = tid & 31;
    const int nrows = Bq * Nq;
    for (int row = blockIdx.x * 8 + w; row < nrows; row += gridDim.x * 8) {
        int b = row >> 12, n = row & (Nq - 1);
        float y2 = g_Y2[(size_t)row * 32 + l] + g_Y2[PS2 + (size_t)row * 32 + l];
        float ym = g_Y1[(size_t)row * 64 + 32 + l] + g_Y1[PS1 + (size_t)row * 64 + 32 + l];

        float acc[3][4];
#pragma unroll
        for (int p = 0; p < 3; p++)
#pragma unroll
            for (int q = 0; q < 4; q++) acc[p][q] = 0.0f;

#pragma unroll
        for (int k = 0; k < 32; k++) {
            float yk2 = __shfl_sync(0xffffffffu, y2, k);
            float ykm = __shfl_sync(0xffffffffu, ym, k);
#pragma unroll
            for (int p = 0; p < 3; p++) {
                float4 wv = Wp[k * 96 + p * 32 + l];
                acc[p][0] = fmaf(yk2, wv.x, acc[p][0]);
                acc[p][1] = fmaf(yk2, wv.y, acc[p][1]);
                acc[p][2] = fmaf(ykm, wv.z, acc[p][2]);
                acc[p][3] = fmaf(ykm, wv.w, acc[p][3]);
            }
        }

        float s[3];
#pragma unroll
        for (int p = 0; p < 3; p++) {
            float4 bb = bp[p * 32 + l];
            float gx = (acc[p][0] + bb.x) * sigf(acc[p][1] + bb.y);
            float gh = (acc[p][2] + bb.z) * sigf(acc[p][3] + bb.w);
            s[p] = gx + gh;
        }
        float i2 = sigf(s[0]);
        float gg = sigf(s[1]);
        float o2 = sigf(s[2]);
        size_t ci = (size_t)row * Fq + l;
        float mo = g_m[ci];
        float mn = i2 * mo + (1.0f - i2) * gg;
        float hn = mn * o2;
        g_m[ci] = mn;
        size_t th = ((size_t)b * 64 + l) * Nq + n;
        size_t tm = ((size_t)b * 64 + 32 + l) * Nq + n;
        __nv_bfloat16 hh = __float2bfloat16(hn);
        __nv_bfloat16 mh = __float2bfloat16(mn);
        g_Sth[th] = hh;
        g_Stl[th] = __float2bfloat16(hn - __bfloat162float(hh));
        g_Sth[tm] = mh;
        g_Stl[tm] = __float2bfloat16(mn - __bfloat162float(mh));
        hidden[(((size_t)b * Tq + t) * Nq + n) * Fq + l] = hn;
        if (t == Tq - 1) {
            last_h[ci] = hn;
            last_m[ci] = mn;
        }
    }
}

// ---------------------------------------------------------------------------
// kernel_launch — forks precompute onto a side stream so it fills the bubbles
// (gates kernels, GEMM tail waves) of the sequential recurrent chain.
// Stream/event objects are host-side resources created once (no device memory).
// ---------------------------------------------------------------------------
extern "C" void kernel_launch(void* const* d_in, const int* in_sizes, int n_in,
                              void* d_out, int out_size) {
    (void)in_sizes; (void)n_in; (void)out_size;
    const float* x    = (const float*)d_in[0];
    const float* adj  = (const float*)d_in[1];
    const float* W    = (const float*)d_in[2];
    const float* bias = (const float*)d_in[3];

    float* hidden = (float*)d_out;
    float* last_h = hidden + (size_t)Bq * Tq * Nq * Fq;
    float* last_c = last_h + (size_t)Bq * Nq * Fq;
    float* last_m = last_c + (size_t)Bq * Nq * Fq;

    float *pYX, *pY1, *pY2;
    __nv_bfloat16 *pxth, *pxtl, *pSth, *pStl, *phth, *phtl;
    cudaGetSymbolAddress((void**)&pYX,  g_YX);
    cudaGetSymbolAddress((void**)&pY1,  g_Y1);
    cudaGetSymbolAddress((void**)&pY2,  g_Y2);
    cudaGetSymbolAddress((void**)&pxth, g_xth);
    cudaGetSymbolAddress((void**)&pxtl, g_xtl);
    cudaGetSymbolAddress((void**)&pSth, g_Sth);
    cudaGetSymbolAddress((void**)&pStl, g_Stl);
    cudaGetSymbolAddress((void**)&phth, g_hth);
    cudaGetSymbolAddress((void**)&phtl, g_htl);

    const int G1_SMEM = (16384 + 512) * 4;
    const int G2_SMEM = (12288 + 384) * 4;
    const int GEMM64_SMEM = 3 * (2 * 128 * 80 + 2 * 64 * 80);  // 92160
    const int GEMM32_SMEM = 3 * (2 * 128 * 80 + 2 * 32 * 80);  // 76800

    static bool inited = false;
    static cudaStream_t s2;
    static cudaEvent_t evFork, evPre[6];
    if (!inited) {
        cudaFuncSetAttribute(gates1_kernel, cudaFuncAttributeMaxDynamicSharedMemorySize, G1_SMEM);
        cudaFuncSetAttribute(gates2_kernel, cudaFuncAttributeMaxDynamicSharedMemorySize, G2_SMEM);
        cudaFuncSetAttribute(adj_gemm_mma<64>, cudaFuncAttributeMaxDynamicSharedMemorySize, GEMM64_SMEM);
        cudaFuncSetAttribute(adj_gemm_mma<32>, cudaFuncAttributeMaxDynamicSharedMemorySize, GEMM32_SMEM);
        cudaStreamCreateWithFlags(&s2, cudaStreamNonBlocking);
        cudaEventCreateWithFlags(&evFork, cudaEventDisableTiming);
        for (int p = 0; p < 6; p++)
            cudaEventCreateWithFlags(&evPre[p], cudaEventDisableTiming);
        inited = true;
    }

    // stream 0 = the harness's capture/launch stream (legacy default works
    // within capture since all our launches use it explicitly).
    cudaStream_t s0 = 0;

    convert_adj<<<(Bq * Nq * Nq / 4) / 256, 256, 0, s0>>>(adj);
    init_state<<<(Bq * 2 * Fq * Nq + 255) / 256, 256, 0, s0>>>();
    trans_split_x<<<dim3(Nq / 64, 1, Bq * Tq), 256, 0, s0>>>(x, pxth, pxtl);

    // Fork: precompute adj @ x on side stream, 6 per-t-pair pieces.
    cudaEventRecord(evFork, s0);
    cudaStreamWaitEvent(s2, evFork, 0);
    for (int p = 0; p < 6; p++) {
        // piece p covers t = 2p, 2p+1 for all 4 batches (grid.z = b)
        adj_gemm_mma<64><<<dim3(Nq / 128, 1, Bq), 256, GEMM64_SMEM, s2>>>(
            pxth + (size_t)p * 64 * Nq, pxtl + (size_t)p * 64 * Nq,
            (long long)Tq * Fq * Nq, 1,
            pYX + (size_t)p * 2 * Nq * Fq, (long long)Tq * Nq * Fq,
            32, (long long)Nq * 32, 0LL, Nq / 32);
        cudaEventRecord(evPre[p], s2);
    }

    const long long PS1 = (long long)Bq * Nq * 64;
    const long long PS2 = (long long)Bq * Nq * 32;
    for (int t = 0; t < Tq; t++) {
        // Y1 = adj @ [h|m]^T   (split-K=2)
        adj_gemm_mma<64><<<dim3(Nq / 128, 2, Bq), 256, GEMM64_SMEM, s0>>>(
            pSth, pStl, (long long)64 * Nq, 1, pY1, (long long)Nq * 64,
            64, 32LL, PS1, Nq / 64);
        // gates1 needs YX[t]: join the matching precompute piece
        if ((t & 1) == 0) cudaStreamWaitEvent(s0, evPre[t >> 1], 0);
        gates1_kernel<<<512, 256, G1_SMEM, s0>>>(W, bias, t, last_c);
        // Y2 = adj @ h_mid^T   (split-K=2)
        adj_gemm_mma<32><<<dim3(Nq / 128, 2, Bq), 256, GEMM32_SMEM, s0>>>(
            phth, phtl, (long long)32 * Nq, 1, pY2, (long long)Nq * 32,
            32, 32LL, PS2, Nq / 64);
        gates2_kernel<<<512, 256, G2_SMEM, s0>>>(W + 8 * (Fq * 2 * Fq), bias + 8 * (2 * Fq),
                                                 t, hidden, last_h, last_m);
    }
}

// round 10
// speedup vs baseline: 1.9725x; 1.1028x over previous
#include <cuda_runtime.h>
#include <cuda_bf16.h>
#include <cstdint>

#define Bq 4
#define Tq 12
#define Nq 4096
#define Fq 32

// ---------------------------------------------------------------------------
// PTX helpers — Ampere-era only (compute_103-safe: tcgen05 rejected by ptxas
// at the compute_103 virtual arch; s8 IMMA slow (R5); term-major order slow
// (R6); 2-stage/3-CTA neutral (R7); >1 extra stream trips the graph-upload
// residue guard (R9)).
// ---------------------------------------------------------------------------
__device__ __forceinline__ uint32_t smem_to_u32(const void* p) {
    uint32_t a;
    asm("{ .reg .u64 t; cvta.to.shared.u64 t, %1; cvt.u32.u64 %0, t; }" : "=r"(a) : "l"(p));
    return a;
}

#define CP_ASYNC16(dst, src) \
    asm volatile("cp.async.cg.shared.global [%0], [%1], 16;" :: "r"(dst), "l"(src) : "memory")
#define CP_COMMIT() asm volatile("cp.async.commit_group;" ::: "memory")
#define CP_WAIT0()  asm volatile("cp.async.wait_group 0;" ::: "memory")
#define CP_WAIT1()  asm volatile("cp.async.wait_group 1;" ::: "memory")
#define CP_WAIT2()  asm volatile("cp.async.wait_group 2;" ::: "memory")

__device__ __forceinline__ void ldsm4(uint32_t addr, uint32_t* r) {
    asm volatile("ldmatrix.sync.aligned.m8n8.x4.shared.b16 {%0,%1,%2,%3}, [%4];"
                 : "=r"(r[0]), "=r"(r[1]), "=r"(r[2]), "=r"(r[3]) : "r"(addr));
}
__device__ __forceinline__ void mma16816(float* d, const uint32_t* a, uint32_t b0, uint32_t b1) {
    asm volatile("mma.sync.aligned.m16n8k16.row.col.f32.bf16.bf16.f32 "
                 "{%0,%1,%2,%3},{%4,%5,%6,%7},{%8,%9},{%0,%1,%2,%3};"
                 : "+f"(d[0]), "+f"(d[1]), "+f"(d[2]), "+f"(d[3])
                 : "r"(a[0]), "r"(a[1]), "r"(a[2]), "r"(a[3]), "r"(b0), "r"(b1));
}

// ---------------------------------------------------------------------------
// Device scratch
// ---------------------------------------------------------------------------
__device__ __align__(128) __nv_bfloat16 g_Ahi[(size_t)Bq * Nq * Nq];
__device__ __align__(128) __nv_bfloat16 g_Alo[(size_t)Bq * Nq * Nq];
__device__ __align__(128) __nv_bfloat16 g_xth[(size_t)Bq * Tq * Fq * Nq];  // [b][t*32+f][n]
__device__ __align__(128) __nv_bfloat16 g_xtl[(size_t)Bq * Tq * Fq * Nq];
__device__ __align__(128) __nv_bfloat16 g_Sth[(size_t)Bq * 2 * Fq * Nq];   // [b][64][n]  (h|m)
__device__ __align__(128) __nv_bfloat16 g_Stl[(size_t)Bq * 2 * Fq * Nq];
__device__ __align__(128) __nv_bfloat16 g_hth[(size_t)Bq * Fq * Nq];       // [b][32][n]  (h_mid)
__device__ __align__(128) __nv_bfloat16 g_htl[(size_t)Bq * Fq * Nq];

__device__ __align__(128) float g_YX[(size_t)Bq * Tq * Nq * Fq];
__device__ __align__(128) float g_Y1[2 * (size_t)Bq * Nq * 2 * Fq];  // split-K=2 partials
__device__ __align__(128) float g_Y2[2 * (size_t)Bq * Nq * Fq];
__device__ __align__(128) float g_m [(size_t)Bq * Nq * Fq];
__device__ __align__(128) float g_c [(size_t)Bq * Nq * Fq];

__device__ __forceinline__ float sigf(float x) { return 1.0f / (1.0f + __expf(-x)); }

// ---------------------------------------------------------------------------
// adj -> bf16 hi/lo split
// ---------------------------------------------------------------------------
__global__ __launch_bounds__(256) void convert_adj(const float* __restrict__ adj) {
    size_t i = (size_t)blockIdx.x * 256 + threadIdx.x;
    float4 v = ((const float4*)adj)[i];
    __nv_bfloat16 h0 = __float2bfloat16(v.x), h1 = __float2bfloat16(v.y);
    __nv_bfloat16 h2 = __float2bfloat16(v.z), h3 = __float2bfloat16(v.w);
    __nv_bfloat16 l0 = __float2bfloat16(v.x - __bfloat162float(h0));
    __nv_bfloat16 l1 = __float2bfloat16(v.y - __bfloat162float(h1));
    __nv_bfloat16 l2 = __float2bfloat16(v.z - __bfloat162float(h2));
    __nv_bfloat16 l3 = __float2bfloat16(v.w - __bfloat162float(h3));
    __nv_bfloat162 hp0 = {h0, h1}, hp1 = {h2, h3}, lp0 = {l0, l1}, lp1 = {l2, l3};
    uint2 hw, lw;
    hw.x = *(uint32_t*)&hp0; hw.y = *(uint32_t*)&hp1;
    lw.x = *(uint32_t*)&lp0; lw.y = *(uint32_t*)&lp1;
    ((uint2*)g_Ahi)[i] = hw;
    ((uint2*)g_Alo)[i] = lw;
}

__global__ void init_state() {
    int i = blockIdx.x * blockDim.x + threadIdx.x;
    if (i < Bq * Nq * Fq) { g_m[i] = 1.0f; g_c[i] = 1.0f; }
    if (i < Bq * 2 * Fq * Nq) {
        g_Sth[i] = __float2bfloat16(1.0f);
        g_Stl[i] = __float2bfloat16(0.0f);
    }
}

// ---------------------------------------------------------------------------
// transpose + bf16 split for x: [z][4096][32] fp32 -> [z][32][4096] bf16 hi/lo
// ---------------------------------------------------------------------------
__global__ __launch_bounds__(256) void trans_split_x(const float* __restrict__ V,
                                                     __nv_bfloat16* __restrict__ Thi,
                                                     __nv_bfloat16* __restrict__ Tlo) {
    __shared__ float tile[64][33];
    const int z = blockIdx.z;
    const int n0 = blockIdx.x * 64;
    const float* v = V + (size_t)z * Nq * 32 + (size_t)n0 * 32;
    const int tid = threadIdx.x;
#pragma unroll
    for (int idx = tid; idx < 64 * 32; idx += 256)
        tile[idx >> 5][idx & 31] = v[idx];
    __syncthreads();
    __nv_bfloat16* th = Thi + (size_t)z * 32 * Nq;
    __nv_bfloat16* tl = Tlo + (size_t)z * 32 * Nq;
#pragma unroll
    for (int idx = tid; idx < 64 * 32; idx += 256) {
        int f = idx >> 6, j = idx & 63;
        float val = tile[j][f];
        __nv_bfloat16 hi = __float2bfloat16(val);
        __nv_bfloat16 lo = __float2bfloat16(val - __bfloat162float(hi));
        th[(size_t)f * Nq + n0 + j] = hi;
        tl[(size_t)f * Nq + n0 + j] = lo;
    }
}

// ---------------------------------------------------------------------------
// split-bf16 mma.sync GEMM with split-K (R4/R8-proven config):
//   Y[part=blockIdx.y][z] = adj[z/adiv][kseg] @ V[z][kseg]
// D = Ahi*Bhi + Ahi*Blo + Alo*Bhi, fp32 register accumulators.
// BM=128, BK=32, 8 warps 4(m) x 2(n), NS-stage cp.async, 2 CTAs/SM,
// per-(mf,nf) interleaved MMA ordering.
// ---------------------------------------------------------------------------
template <int BN, int NS>
__global__ __launch_bounds__(256, 2) void adj_gemm_mma(
    const __nv_bfloat16* __restrict__ Bhi_g, const __nv_bfloat16* __restrict__ Blo_g,
    long long bZ, int adiv, float* __restrict__ Y, long long yZ,
    int rstride, long long gstride, long long partStride, int nch) {
    constexpr int RB = 80;                 // 64B data + 16B pad
    constexpr int A_BYTES = 128 * RB;
    constexpr int B_BYTES = BN * RB;
    constexpr int OFF_AH = 0, OFF_AL = A_BYTES;
    constexpr int OFF_BH = 2 * A_BYTES, OFF_BL = 2 * A_BYTES + B_BYTES;
    constexpr int STAGE = 2 * A_BYTES + 2 * B_BYTES;
    constexpr int WN = BN / 2;
    constexpr int NF = WN / 8;
    constexpr int NB = (NF + 1) / 2;

    extern __shared__ char smc[];
    const uint32_t sbase = smem_to_u32(smc);
    const int tid = threadIdx.x;
    const int wid = tid >> 5, lane = tid & 31;
    const int wm = wid & 3, wn = wid >> 2;
    const int z = blockIdx.z;
    const int m0 = blockIdx.x * 128;
    const int kbase = blockIdx.y * nch * 32;

    const __nv_bfloat16* gAh = g_Ahi + (size_t)(z / adiv) * Nq * Nq + (size_t)m0 * Nq + kbase;
    const __nv_bfloat16* gAl = g_Alo + (size_t)(z / adiv) * Nq * Nq + (size_t)m0 * Nq + kbase;
    const __nv_bfloat16* gBh = Bhi_g + (size_t)z * bZ + kbase;
    const __nv_bfloat16* gBl = Blo_g + (size_t)z * bZ + kbase;

    const int arow = tid >> 2;
    const int acol = tid & 3;
    const int brow = tid >> 2;
    const bool bact = (BN == 64) || (tid < 128);

    float acc[2][NF][4];
#pragma unroll
    for (int mf = 0; mf < 2; mf++)
#pragma unroll
        for (int nf = 0; nf < NF; nf++)
#pragma unroll
            for (int q = 0; q < 4; q++) acc[mf][nf][q] = 0.0f;

    auto issue = [&](int c) {
        const uint32_t st = sbase + (uint32_t)(c % NS) * STAGE;
        const int k0 = c * 32;
#pragma unroll
        for (int rep = 0; rep < 2; rep++) {
            int r = rep * 64 + arow;
            uint32_t d = st + r * RB + acol * 16;
            CP_ASYNC16(d + OFF_AH, gAh + (size_t)r * Nq + k0 + acol * 8);
            CP_ASYNC16(d + OFF_AL, gAl + (size_t)r * Nq + k0 + acol * 8);
        }
        if (bact) {
            uint32_t d = st + brow * RB + acol * 16;
            CP_ASYNC16(d + OFF_BH, gBh + (size_t)brow * Nq + k0 + acol * 8);
            CP_ASYNC16(d + OFF_BL, gBl + (size_t)brow * Nq + k0 + acol * 8);
        }
    };

    // prologue: fill NS-1 stages
    issue(0); CP_COMMIT();
    issue(1); CP_COMMIT();
    if (NS == 4 && nch > 2) { issue(2); CP_COMMIT(); }

    const int a_r = (lane & 15);
    const int a_k = (lane >> 4) * 16;
    const int b_r = ((lane >> 4) << 3) + (lane & 7);
    const int b_k = ((lane >> 3) & 1) * 16;

#pragma unroll 1
    for (int c = 0; c < nch; c++) {
        const int rem = nch - 1 - c;  // groups issued beyond c (at most NS-2)
        if (rem >= NS - 2) {
            if (NS == 4) { CP_WAIT2(); } else { CP_WAIT1(); }
        } else if (rem == 1) { CP_WAIT1(); }
        else { CP_WAIT0(); }
        __syncthreads();
        if (c + NS - 1 < nch) { issue(c + NS - 1); CP_COMMIT(); }

        const uint32_t st = sbase + (uint32_t)(c % NS) * STAGE;
#pragma unroll
        for (int ks = 0; ks < 2; ks++) {
            uint32_t ah[2][4], al[2][4];
#pragma unroll
            for (int mf = 0; mf < 2; mf++) {
                uint32_t addr = st + (wm * 32 + mf * 16 + a_r) * RB + ks * 32 + a_k;
                ldsm4(addr + OFF_AH, ah[mf]);
                ldsm4(addr + OFF_AL, al[mf]);
            }
            uint32_t bh[NB][4], bl[NB][4];
#pragma unroll
            for (int nb = 0; nb < NB; nb++) {
                uint32_t addr = st + (wn * WN + nb * 16 + b_r) * RB + ks * 32 + b_k;
                ldsm4(addr + OFF_BH, bh[nb]);
                ldsm4(addr + OFF_BL, bl[nb]);
            }
#pragma unroll
            for (int mf = 0; mf < 2; mf++)
#pragma unroll
                for (int nf = 0; nf < NF; nf++) {
                    const int nb = nf >> 1, pr = (nf & 1) * 2;
                    mma16816(acc[mf][nf], ah[mf], bh[nb][pr], bh[nb][pr + 1]);
                    mma16816(acc[mf][nf], ah[mf], bl[nb][pr], bl[nb][pr + 1]);
                    mma16816(acc[mf][nf], al[mf], bh[nb][pr], bh[nb][pr + 1]);
                }
        }
    }

    float* yb = Y + (size_t)blockIdx.y * partStride + (size_t)z * yZ;
#pragma unroll
    for (int mf = 0; mf < 2; mf++)
#pragma unroll
        for (int nf = 0; nf < NF; nf++) {
            int r = m0 + wm * 32 + mf * 16 + (lane >> 2);
            int cj = wn * WN + nf * 8 + (lane & 3) * 2;
            size_t off = (size_t)(cj >> 5) * gstride + (cj & 31);
            float* o0 = yb + (size_t)r * rstride + off;
            float* o1 = yb + (size_t)(r + 8) * rstride + off;
            *(float2*)o0 = make_float2(acc[mf][nf][0], acc[mf][nf][1]);
            *(float2*)o1 = make_float2(acc[mf][nf][2], acc[mf][nf][3]);
        }
}

// ---------------------------------------------------------------------------
// gates1: LSTM gates 0..7, ROW-BLOCKED (4 rows per warp per k-sweep: one W
// LDS.128 feeds 16 FMAs -> crossbar traffic /4, kernel goes FMA-bound).
// Sums 2 split-K partials; writes h_mid transposed bf16 hi/lo.
// Per-row FMA order identical to previous rounds -> bitwise-same results.
// ---------------------------------------------------------------------------
__global__ __launch_bounds__(256) void gates1_kernel(const float* __restrict__ W,
                                                     const float* __restrict__ bias,
                                                     int t, float* __restrict__ last_c) {
    extern __shared__ float sm[];
    float4* Wp = (float4*)sm;
    float4* bp = (float4*)(sm + 16384);
    const long long PS1 = (long long)Bq * Nq * 64;

    const int tid = threadIdx.x;
    for (int idx = tid; idx < 4096; idx += 256) {
        int l = idx & 31, p = (idx >> 5) & 3, k = idx >> 7;
        const float* W0 = W + (2 * p) * (Fq * 2 * Fq) + k * (2 * Fq);
        const float* W1 = W + (2 * p + 1) * (Fq * 2 * Fq) + k * (2 * Fq);
        Wp[idx] = make_float4(W0[l], W0[l + 32], W1[l], W1[l + 32]);
    }
    if (tid < 128) {
        int l = tid & 31, p = tid >> 5;
        bp[p * 32 + l] = make_float4(bias[(2 * p) * 64 + l], bias[(2 * p) * 64 + 32 + l],
                                     bias[(2 * p + 1) * 64 + l], bias[(2 * p + 1) * 64 + 32 + l]);
    }
    __syncthreads();

    const int w = tid >> 5, l = tid & 31;
    const int nrows = Bq * Nq;
#pragma unroll 1
    for (int r0 = blockIdx.x * 32 + w * 4; r0 < nrows; r0 += gridDim.x * 32) {
        float yx[4], yh[4];
#pragma unroll
        for (int i = 0; i < 4; i++) {
            int row = r0 + i;
            int b = row >> 12, n = row & (Nq - 1);
            yx[i] = g_YX[(((size_t)b * Tq + t) * Nq + n) * Fq + l];
            yh[i] = g_Y1[(size_t)row * 64 + l] + g_Y1[PS1 + (size_t)row * 64 + l];
        }

        float acc[4][4][4];
#pragma unroll
        for (int i = 0; i < 4; i++)
#pragma unroll
            for (int p = 0; p < 4; p++)
#pragma unroll
                for (int q = 0; q < 4; q++) acc[i][p][q] = 0.0f;

#pragma unroll
        for (int k = 0; k < 32; k++) {
            float ykx[4], ykh[4];
#pragma unroll
            for (int i = 0; i < 4; i++) {
                ykx[i] = __shfl_sync(0xffffffffu, yx[i], k);
                ykh[i] = __shfl_sync(0xffffffffu, yh[i], k);
            }
#pragma unroll
            for (int p = 0; p < 4; p++) {
                float4 wv = Wp[k * 128 + p * 32 + l];
#pragma unroll
                for (int i = 0; i < 4; i++) {
                    acc[i][p][0] = fmaf(ykx[i], wv.x, acc[i][p][0]);
                    acc[i][p][1] = fmaf(ykx[i], wv.y, acc[i][p][1]);
                    acc[i][p][2] = fmaf(ykh[i], wv.z, acc[i][p][2]);
                    acc[i][p][3] = fmaf(ykh[i], wv.w, acc[i][p][3]);
                }
            }
        }

#pragma unroll
        for (int i = 0; i < 4; i++) {
            int row = r0 + i;
            int b = row >> 12, n = row & (Nq - 1);
            float s[4];
#pragma unroll
            for (int p = 0; p < 4; p++) {
                float4 bb = bp[p * 32 + l];
                float gx = (acc[i][p][0] + bb.x) * sigf(acc[i][p][1] + bb.y);
                float gh = (acc[i][p][2] + bb.z) * sigf(acc[i][p][3] + bb.w);
                s[p] = gx + gh;
            }
            float f  = sigf(s[0]);
            float ig = sigf(s[1]);
            float o  = sigf(s[3]);
            size_t ci = (size_t)row * Fq + l;
            float cn = f * g_c[ci] + ig * tanhf(s[2]);
            g_c[ci] = cn;
            float hm = o * tanhf(cn);
            size_t ti = ((size_t)b * Fq + l) * Nq + n;
            __nv_bfloat16 hi = __float2bfloat16(hm);
            g_hth[ti] = hi;
            g_htl[ti] = __float2bfloat16(hm - __bfloat162float(hi));
            if (t == Tq - 1) last_c[ci] = cn;
        }
    }
}

// ---------------------------------------------------------------------------
// gates2: memory gates 8..13, ROW-BLOCKED; sums 2 split-K partials; writes
// new [h|m] transposed bf16 hi/lo.
// ---------------------------------------------------------------------------
__global__ __launch_bounds__(256) void gates2_kernel(const float* __restrict__ W8,
                                                     const float* __restrict__ bias8,
                                                     int t, float* __restrict__ hidden,
                                                     float* __restrict__ last_h,
                                                     float* __restrict__ last_m) {
    extern __shared__ float sm[];
    float4* Wp = (float4*)sm;
    float4* bp = (float4*)(sm + 12288);
    const long long PS1 = (long long)Bq * Nq * 64;
    const long long PS2 = (long long)Bq * Nq * 32;

    const int tid = threadIdx.x;
    for (int idx = tid; idx < 3072; idx += 256) {
        int k = idx / 96, r = idx % 96, p = r >> 5, l = r & 31;
        const float* W0 = W8 + (2 * p) * (Fq * 2 * Fq) + k * (2 * Fq);
        const float* W1 = W8 + (2 * p + 1) * (Fq * 2 * Fq) + k * (2 * Fq);
        Wp[idx] = make_float4(W0[l], W0[l + 32], W1[l], W1[l + 32]);
    }
    if (tid < 96) {
        int p = tid >> 5, l = tid & 31;
        bp[tid] = make_float4(bias8[(2 * p) * 64 + l], bias8[(2 * p) * 64 + 32 + l],
                              bias8[(2 * p + 1) * 64 + l], bias8[(2 * p + 1) * 64 + 32 + l]);
    }
    __syncthreads();

    const int w = tid >> 5, l = tid & 31;
    const int nrows = Bq * Nq;
#pragma unroll 1
    for (int r0 = blockIdx.x * 32 + w * 4; r0 < nrows; r0 += gridDim.x * 32) {
        float y2[4], ym[4];
#pragma unroll
        for (int i = 0; i < 4; i++) {
            int row = r0 + i;
            y2[i] = g_Y2[(size_t)row * 32 + l] + g_Y2[PS2 + (size_t)row * 32 + l];
            ym[i] = g_Y1[(size_t)row * 64 + 32 + l] + g_Y1[PS1 + (size_t)row * 64 + 32 + l];
        }

        float acc[4][3][4];
#pragma unroll
        for (int i = 0; i < 4; i++)
#pragma unroll
            for (int p = 0; p < 3; p++)
#pragma unroll
                for (int q = 0; q < 4; q++) acc[i][p][q] = 0.0f;

#pragma unroll
        for (int k = 0; k < 32; k++) {
            float yk2[4], ykm[4];
#pragma unroll
            for (int i = 0; i < 4; i++) {
                yk2[i] = __shfl_sync(0xffffffffu, y2[i], k);
                ykm[i] = __shfl_sync(0xffffffffu, ym[i], k);
            }
#pragma unroll
            for (int p = 0; p < 3; p++) {
                float4 wv = Wp[k * 96 + p * 32 + l];
#pragma unroll
                for (int i = 0; i < 4; i++) {
                    acc[i][p][0] = fmaf(yk2[i], wv.x, acc[i][p][0]);
                    acc[i][p][1] = fmaf(yk2[i], wv.y, acc[i][p][1]);
                    acc[i][p][2] = fmaf(ykm[i], wv.z, acc[i][p][2]);
                    acc[i][p][3] = fmaf(ykm[i], wv.w, acc[i][p][3]);
                }
            }
        }

#pragma unroll
        for (int i = 0; i < 4; i++) {
            int row = r0 + i;
            int b = row >> 12, n = row & (Nq - 1);
            float s[3];
#pragma unroll
            for (int p = 0; p < 3; p++) {
                float4 bb = bp[p * 32 + l];
                float gx = (acc[i][p][0] + bb.x) * sigf(acc[i][p][1] + bb.y);
                float gh = (acc[i][p][2] + bb.z) * sigf(acc[i][p][3] + bb.w);
                s[p] = gx + gh;
            }
            float i2 = sigf(s[0]);
            float gg = sigf(s[1]);
            float o2 = sigf(s[2]);
            size_t ci = (size_t)row * Fq + l;
            float mo = g_m[ci];
            float mn = i2 * mo + (1.0f - i2) * gg;
            float hn = mn * o2;
            g_m[ci] = mn;
            size_t th = ((size_t)b * 64 + l) * Nq + n;
            size_t tm = ((size_t)b * 64 + 32 + l) * Nq + n;
            __nv_bfloat16 hh = __float2bfloat16(hn);
            __nv_bfloat16 mh = __float2bfloat16(mn);
            g_Sth[th] = hh;
            g_Stl[th] = __float2bfloat16(hn - __bfloat162float(hh));
            g_Sth[tm] = mh;
            g_Stl[tm] = __float2bfloat16(mn - __bfloat162float(mh));
            hidden[(((size_t)b * Tq + t) * Nq + n) * Fq + l] = hn;
            if (t == Tq - 1) {
                last_h[ci] = hn;
                last_m[ci] = mn;
            }
        }
    }
}

// ---------------------------------------------------------------------------
// kernel_launch — R8 structure (one side stream for precompute; passed the
// allocation guard) + row-blocked gates + 4-stage Y2.
// ---------------------------------------------------------------------------
extern "C" void kernel_launch(void* const* d_in, const int* in_sizes, int n_in,
                              void* d_out, int out_size) {
    (void)in_sizes; (void)n_in; (void)out_size;
    const float* x    = (const float*)d_in[0];
    const float* adj  = (const float*)d_in[1];
    const float* W    = (const float*)d_in[2];
    const float* bias = (const float*)d_in[3];

    float* hidden = (float*)d_out;
    float* last_h = hidden + (size_t)Bq * Tq * Nq * Fq;
    float* last_c = last_h + (size_t)Bq * Nq * Fq;
    float* last_m = last_c + (size_t)Bq * Nq * Fq;

    float *pYX, *pY1, *pY2;
    __nv_bfloat16 *pxth, *pxtl, *pSth, *pStl, *phth, *phtl;
    cudaGetSymbolAddress((void**)&pYX,  g_YX);
    cudaGetSymbolAddress((void**)&pY1,  g_Y1);
    cudaGetSymbolAddress((void**)&pY2,  g_Y2);
    cudaGetSymbolAddress((void**)&pxth, g_xth);
    cudaGetSymbolAddress((void**)&pxtl, g_xtl);
    cudaGetSymbolAddress((void**)&pSth, g_Sth);
    cudaGetSymbolAddress((void**)&pStl, g_Stl);
    cudaGetSymbolAddress((void**)&phth, g_hth);
    cudaGetSymbolAddress((void**)&phtl, g_htl);

    const int G1_SMEM = (16384 + 512) * 4;
    const int G2_SMEM = (12288 + 384) * 4;
    const int GEMM64_SMEM = 3 * (2 * 128 * 80 + 2 * 64 * 80);  // 92160 (3-stage)
    const int GEMM32_SMEM = 4 * (2 * 128 * 80 + 2 * 32 * 80);  // 102400 (4-stage)

    static bool inited = false;
    static cudaStream_t s2;
    static cudaEvent_t evFork, evPre[6];
    if (!inited) {
        cudaFuncSetAttribute(gates1_kernel, cudaFuncAttributeMaxDynamicSharedMemorySize, G1_SMEM);
        cudaFuncSetAttribute(gates2_kernel, cudaFuncAttributeMaxDynamicSharedMemorySize, G2_SMEM);
        cudaFuncSetAttribute((void*)adj_gemm_mma<64, 3>,
                             cudaFuncAttributeMaxDynamicSharedMemorySize, GEMM64_SMEM);
        cudaFuncSetAttribute((void*)adj_gemm_mma<32, 4>,
                             cudaFuncAttributeMaxDynamicSharedMemorySize, GEMM32_SMEM);
        cudaStreamCreateWithFlags(&s2, cudaStreamNonBlocking);
        cudaEventCreateWithFlags(&evFork, cudaEventDisableTiming);
        for (int p = 0; p < 6; p++)
            cudaEventCreateWithFlags(&evPre[p], cudaEventDisableTiming);
        inited = true;
    }

    cudaStream_t s0 = 0;

    convert_adj<<<(Bq * Nq * Nq / 4) / 256, 256, 0, s0>>>(adj);
    init_state<<<(Bq * 2 * Fq * Nq + 255) / 256, 256, 0, s0>>>();
    trans_split_x<<<dim3(Nq / 64, 1, Bq * Tq), 256, 0, s0>>>(x, pxth, pxtl);

    // Fork: precompute adj @ x on side stream, 6 per-t-pair pieces.
    cudaEventRecord(evFork, s0);
    cudaStreamWaitEvent(s2, evFork, 0);
    for (int p = 0; p < 6; p++) {
        adj_gemm_mma<64, 3><<<dim3(Nq / 128, 1, Bq), 256, GEMM64_SMEM, s2>>>(
            pxth + (size_t)p * 64 * Nq, pxtl + (size_t)p * 64 * Nq,
            (long long)Tq * Fq * Nq, 1,
            pYX + (size_t)p * 2 * Nq * Fq, (long long)Tq * Nq * Fq,
            32, (long long)Nq * 32, 0LL, Nq / 32);
        cudaEventRecord(evPre[p], s2);
    }

    const long long PS1 = (long long)Bq * Nq * 64;
    const long long PS2 = (long long)Bq * Nq * 32;
    for (int t = 0; t < Tq; t++) {
        // Y1 = adj @ [h|m]^T   (split-K=2, 3-stage)
        adj_gemm_mma<64, 3><<<dim3(Nq / 128, 2, Bq), 256, GEMM64_SMEM, s0>>>(
            pSth, pStl, (long long)64 * Nq, 1, pY1, (long long)Nq * 64,
            64, 32LL, PS1, Nq / 64);
        // gates1 needs YX[t]: join the matching precompute piece
        if ((t & 1) == 0) cudaStreamWaitEvent(s0, evPre[t >> 1], 0);
        gates1_kernel<<<128, 256, G1_SMEM, s0>>>(W, bias, t, last_c);
        // Y2 = adj @ h_mid^T   (split-K=2, 4-stage)
        adj_gemm_mma<32, 4><<<dim3(Nq / 128, 2, Bq), 256, GEMM32_SMEM, s0>>>(
            phth, phtl, (long long)32 * Nq, 1, pY2, (long long)Nq * 32,
            32, 32LL, PS2, Nq / 64);
        gates2_kernel<<<128, 256, G2_SMEM, s0>>>(W + 8 * (Fq * 2 * Fq), bias + 8 * (2 * Fq),
                                                 t, hidden, last_h, last_m);
    }
}

// round 11
// speedup vs baseline: 3.1034x; 1.5734x over previous
#include <cuda_runtime.h>
#include <cuda_fp16.h>
#include <cstdint>

#define Bq 4
#define Tq 12
#define Nq 4096
#define Fq 32

// ---------------------------------------------------------------------------
// PTX helpers — Ampere-era only (compute_103-safe: tcgen05 rejected by ptxas
// at the compute_103 virtual arch; s8 IMMA slow (R5); term-major order slow
// (R6); extra-stream-per-batch graphs trip the upload-residue guard (R9)).
// ---------------------------------------------------------------------------
__device__ __forceinline__ uint32_t smem_to_u32(const void* p) {
    uint32_t a;
    asm("{ .reg .u64 t; cvta.to.shared.u64 t, %1; cvt.u32.u64 %0, t; }" : "=r"(a) : "l"(p));
    return a;
}

#define CP_ASYNC16(dst, src) \
    asm volatile("cp.async.cg.shared.global [%0], [%1], 16;" :: "r"(dst), "l"(src) : "memory")
#define CP_COMMIT() asm volatile("cp.async.commit_group;" ::: "memory")
#define CP_WAIT0()  asm volatile("cp.async.wait_group 0;" ::: "memory")
#define CP_WAIT1()  asm volatile("cp.async.wait_group 1;" ::: "memory")
#define CP_WAIT2()  asm volatile("cp.async.wait_group 2;" ::: "memory")

__device__ __forceinline__ void ldsm4(uint32_t addr, uint32_t* r) {
    asm volatile("ldmatrix.sync.aligned.m8n8.x4.shared.b16 {%0,%1,%2,%3}, [%4];"
                 : "=r"(r[0]), "=r"(r[1]), "=r"(r[2]), "=r"(r[3]) : "r"(addr));
}
__device__ __forceinline__ void mma_f16(float* d, const uint32_t* a, uint32_t b0, uint32_t b1) {
    asm volatile("mma.sync.aligned.m16n8k16.row.col.f32.f16.f16.f32 "
                 "{%0,%1,%2,%3},{%4,%5,%6,%7},{%8,%9},{%0,%1,%2,%3};"
                 : "+f"(d[0]), "+f"(d[1]), "+f"(d[2]), "+f"(d[3])
                 : "r"(a[0]), "r"(a[1]), "r"(a[2]), "r"(a[3]), "r"(b0), "r"(b1));
}

// ---------------------------------------------------------------------------
// Device scratch (single fp16 operands — no hi/lo splits; see R11 error model)
// ---------------------------------------------------------------------------
__device__ __align__(128) __half g_Ah[(size_t)Bq * Nq * Nq];
__device__ __align__(128) __half g_xt[(size_t)Bq * Tq * Fq * Nq];   // [b][t*32+f][n]
__device__ __align__(128) __half g_St[(size_t)Bq * 2 * Fq * Nq];    // [b][64][n]  (h|m)
__device__ __align__(128) __half g_ht[(size_t)Bq * Fq * Nq];        // [b][32][n]  (h_mid)

__device__ __align__(128) float g_YX[(size_t)Bq * Tq * Nq * Fq];
__device__ __align__(128) float g_Y1[2 * (size_t)Bq * Nq * 2 * Fq]; // split-K=2 partials
__device__ __align__(128) float g_Y2[2 * (size_t)Bq * Nq * Fq];
__device__ __align__(128) float g_m [(size_t)Bq * Nq * Fq];
__device__ __align__(128) float g_c [(size_t)Bq * Nq * Fq];

__device__ __forceinline__ float sigf(float x) { return 1.0f / (1.0f + __expf(-x)); }

// ---------------------------------------------------------------------------
// adj -> fp16
// ---------------------------------------------------------------------------
__global__ __launch_bounds__(256) void convert_adj(const float* __restrict__ adj) {
    size_t i = (size_t)blockIdx.x * 256 + threadIdx.x;
    float4 v = ((const float4*)adj)[i];
    __half2 p0 = __floats2half2_rn(v.x, v.y);
    __half2 p1 = __floats2half2_rn(v.z, v.w);
    uint2 w;
    w.x = *(uint32_t*)&p0; w.y = *(uint32_t*)&p1;
    ((uint2*)g_Ah)[i] = w;
}

__global__ void init_state() {
    int i = blockIdx.x * blockDim.x + threadIdx.x;
    if (i < Bq * Nq * Fq) { g_m[i] = 1.0f; g_c[i] = 1.0f; }
    if (i < Bq * 2 * Fq * Nq) g_St[i] = __float2half(1.0f);
}

// ---------------------------------------------------------------------------
// transpose x: [z][4096][32] fp32 -> [z][32][4096] fp16
// ---------------------------------------------------------------------------
__global__ __launch_bounds__(256) void trans_x(const float* __restrict__ V,
                                               __half* __restrict__ T) {
    __shared__ float tile[64][33];
    const int z = blockIdx.z;
    const int n0 = blockIdx.x * 64;
    const float* v = V + (size_t)z * Nq * 32 + (size_t)n0 * 32;
    const int tid = threadIdx.x;
#pragma unroll
    for (int idx = tid; idx < 64 * 32; idx += 256)
        tile[idx >> 5][idx & 31] = v[idx];
    __syncthreads();
    __half* t = T + (size_t)z * 32 * Nq;
#pragma unroll
    for (int idx = tid; idx < 64 * 32; idx += 256) {
        int f = idx >> 6, j = idx & 63;
        t[(size_t)f * Nq + n0 + j] = __float2half(tile[j][f]);
    }
}

// ---------------------------------------------------------------------------
// single-term fp16 mma.sync GEMM with split-K:
//   Y[part=blockIdx.y][z] = adj[z/adiv][kseg] @ V[z][kseg]
// BM=128, BK=32, 8 warps 4(m) x 2(n), 4-stage cp.async, 2 CTAs/SM,
// fp32 accumulators.
// ---------------------------------------------------------------------------
template <int BN>
__global__ __launch_bounds__(256, 2) void adj_gemm_mma(
    const __half* __restrict__ B_g,
    long long bZ, int adiv, float* __restrict__ Y, long long yZ,
    int rstride, long long gstride, long long partStride, int nch) {
    constexpr int NS = 4;
    constexpr int RB = 80;                 // 64B data + 16B pad
    constexpr int A_BYTES = 128 * RB;      // 10240
    constexpr int B_BYTES = BN * RB;
    constexpr int OFF_B = A_BYTES;
    constexpr int STAGE = A_BYTES + B_BYTES;
    constexpr int WN = BN / 2;
    constexpr int NF = WN / 8;
    constexpr int NB = (NF + 1) / 2;

    extern __shared__ char smc[];
    const uint32_t sbase = smem_to_u32(smc);
    const int tid = threadIdx.x;
    const int wid = tid >> 5, lane = tid & 31;
    const int wm = wid & 3, wn = wid >> 2;
    const int z = blockIdx.z;
    const int m0 = blockIdx.x * 128;
    const int kbase = blockIdx.y * nch * 32;

    const __half* gA = g_Ah + (size_t)(z / adiv) * Nq * Nq + (size_t)m0 * Nq + kbase;
    const __half* gB = B_g + (size_t)z * bZ + kbase;

    const int arow = tid >> 2;             // 0..63, +64 for rep 1
    const int acol = tid & 3;
    const int brow = (BN == 64) ? (tid >> 2) : ((tid & 127) >> 2);
    const bool bact = (BN == 64) || (tid < 128);

    float acc[2][NF][4];
#pragma unroll
    for (int mf = 0; mf < 2; mf++)
#pragma unroll
        for (int nf = 0; nf < NF; nf++)
#pragma unroll
            for (int q = 0; q < 4; q++) acc[mf][nf][q] = 0.0f;

    auto issue = [&](int c) {
        const uint32_t st = sbase + (uint32_t)(c % NS) * STAGE;
        const int k0 = c * 32;
#pragma unroll
        for (int rep = 0; rep < 2; rep++) {
            int r = rep * 64 + arow;
            CP_ASYNC16(st + r * RB + acol * 16, gA + (size_t)r * Nq + k0 + acol * 8);
        }
        if (bact)
            CP_ASYNC16(st + OFF_B + brow * RB + acol * 16,
                       gB + (size_t)brow * Nq + k0 + acol * 8);
    };

    // prologue: fill NS-1 stages (nch >= 32 always here)
    issue(0); CP_COMMIT();
    issue(1); CP_COMMIT();
    issue(2); CP_COMMIT();

    const int a_r = (lane & 15);
    const int a_k = (lane >> 4) * 16;
    const int b_r = ((lane >> 4) << 3) + (lane & 7);
    const int b_k = ((lane >> 3) & 1) * 16;

#pragma unroll 1
    for (int c = 0; c < nch; c++) {
        const int rem = nch - 1 - c;
        if (rem >= NS - 2) { CP_WAIT2(); }
        else if (rem == 1) { CP_WAIT1(); }
        else { CP_WAIT0(); }
        __syncthreads();
        if (c + NS - 1 < nch) { issue(c + NS - 1); CP_COMMIT(); }

        const uint32_t st = sbase + (uint32_t)(c % NS) * STAGE;
#pragma unroll
        for (int ks = 0; ks < 2; ks++) {
            uint32_t ah[2][4];
#pragma unroll
            for (int mf = 0; mf < 2; mf++) {
                uint32_t addr = st + (wm * 32 + mf * 16 + a_r) * RB + ks * 32 + a_k;
                ldsm4(addr, ah[mf]);
            }
            uint32_t bh[NB][4];
#pragma unroll
            for (int nb = 0; nb < NB; nb++) {
                uint32_t addr = st + OFF_B + (wn * WN + nb * 16 + b_r) * RB + ks * 32 + b_k;
                ldsm4(addr, bh[nb]);
            }
#pragma unroll
            for (int mf = 0; mf < 2; mf++)
#pragma unroll
                for (int nf = 0; nf < NF; nf++) {
                    const int nb = nf >> 1, pr = (nf & 1) * 2;
                    mma_f16(acc[mf][nf], ah[mf], bh[nb][pr], bh[nb][pr + 1]);
                }
        }
    }

    float* yb = Y + (size_t)blockIdx.y * partStride + (size_t)z * yZ;
#pragma unroll
    for (int mf = 0; mf < 2; mf++)
#pragma unroll
        for (int nf = 0; nf < NF; nf++) {
            int r = m0 + wm * 32 + mf * 16 + (lane >> 2);
            int cj = wn * WN + nf * 8 + (lane & 3) * 2;
            size_t off = (size_t)(cj >> 5) * gstride + (cj & 31);
            float* o0 = yb + (size_t)r * rstride + off;
            float* o1 = yb + (size_t)(r + 8) * rstride + off;
            *(float2*)o0 = make_float2(acc[mf][nf][0], acc[mf][nf][1]);
            *(float2*)o1 = make_float2(acc[mf][nf][2], acc[mf][nf][3]);
        }
}

// ---------------------------------------------------------------------------
// gates1: LSTM gates 0..7, row-blocked (R10-proven); sums 2 split-K partials;
// writes h_mid transposed fp16.
// ---------------------------------------------------------------------------
__global__ __launch_bounds__(256) void gates1_kernel(const float* __restrict__ W,
                                                     const float* __restrict__ bias,
                                                     int t, float* __restrict__ last_c) {
    extern __shared__ float sm[];
    float4* Wp = (float4*)sm;
    float4* bp = (float4*)(sm + 16384);
    const long long PS1 = (long long)Bq * Nq * 64;

    const int tid = threadIdx.x;
    for (int idx = tid; idx < 4096; idx += 256) {
        int l = idx & 31, p = (idx >> 5) & 3, k = idx >> 7;
        const float* W0 = W + (2 * p) * (Fq * 2 * Fq) + k * (2 * Fq);
        const float* W1 = W + (2 * p + 1) * (Fq * 2 * Fq) + k * (2 * Fq);
        Wp[idx] = make_float4(W0[l], W0[l + 32], W1[l], W1[l + 32]);
    }
    if (tid < 128) {
        int l = tid & 31, p = tid >> 5;
        bp[p * 32 + l] = make_float4(bias[(2 * p) * 64 + l], bias[(2 * p) * 64 + 32 + l],
                                     bias[(2 * p + 1) * 64 + l], bias[(2 * p + 1) * 64 + 32 + l]);
    }
    __syncthreads();

    const int w = tid >> 5, l = tid & 31;
    const int nrows = Bq * Nq;
#pragma unroll 1
    for (int r0 = blockIdx.x * 32 + w * 4; r0 < nrows; r0 += gridDim.x * 32) {
        float yx[4], yh[4];
#pragma unroll
        for (int i = 0; i < 4; i++) {
            int row = r0 + i;
            int b = row >> 12, n = row & (Nq - 1);
            yx[i] = g_YX[(((size_t)b * Tq + t) * Nq + n) * Fq + l];
            yh[i] = g_Y1[(size_t)row * 64 + l] + g_Y1[PS1 + (size_t)row * 64 + l];
        }

        float acc[4][4][4];
#pragma unroll
        for (int i = 0; i < 4; i++)
#pragma unroll
            for (int p = 0; p < 4; p++)
#pragma unroll
                for (int q = 0; q < 4; q++) acc[i][p][q] = 0.0f;

#pragma unroll
        for (int k = 0; k < 32; k++) {
            float ykx[4], ykh[4];
#pragma unroll
            for (int i = 0; i < 4; i++) {
                ykx[i] = __shfl_sync(0xffffffffu, yx[i], k);
                ykh[i] = __shfl_sync(0xffffffffu, yh[i], k);
            }
#pragma unroll
            for (int p = 0; p < 4; p++) {
                float4 wv = Wp[k * 128 + p * 32 + l];
#pragma unroll
                for (int i = 0; i < 4; i++) {
                    acc[i][p][0] = fmaf(ykx[i], wv.x, acc[i][p][0]);
                    acc[i][p][1] = fmaf(ykx[i], wv.y, acc[i][p][1]);
                    acc[i][p][2] = fmaf(ykh[i], wv.z, acc[i][p][2]);
                    acc[i][p][3] = fmaf(ykh[i], wv.w, acc[i][p][3]);
                }
            }
        }

#pragma unroll
        for (int i = 0; i < 4; i++) {
            int row = r0 + i;
            int b = row >> 12, n = row & (Nq - 1);
            float s[4];
#pragma unroll
            for (int p = 0; p < 4; p++) {
                float4 bb = bp[p * 32 + l];
                float gx = (acc[i][p][0] + bb.x) * sigf(acc[i][p][1] + bb.y);
                float gh = (acc[i][p][2] + bb.z) * sigf(acc[i][p][3] + bb.w);
                s[p] = gx + gh;
            }
            float f  = sigf(s[0]);
            float ig = sigf(s[1]);
            float o  = sigf(s[3]);
            size_t ci = (size_t)row * Fq + l;
            float cn = f * g_c[ci] + ig * tanhf(s[2]);
            g_c[ci] = cn;
            float hm = o * tanhf(cn);
            g_ht[((size_t)b * Fq + l) * Nq + n] = __float2half(hm);
            if (t == Tq - 1) last_c[ci] = cn;
        }
    }
}

// ---------------------------------------------------------------------------
// gates2: memory gates 8..13, row-blocked; sums 2 split-K partials; writes
// new [h|m] transposed fp16.
// ---------------------------------------------------------------------------
__global__ __launch_bounds__(256) void gates2_kernel(const float* __restrict__ W8,
                                                     const float* __restrict__ bias8,
                                                     int t, float* __restrict__ hidden,
                                                     float* __restrict__ last_h,
                                                     float* __restrict__ last_m) {
    extern __shared__ float sm[];
    float4* Wp = (float4*)sm;
    float4* bp = (float4*)(sm + 12288);
    const long long PS1 = (long long)Bq * Nq * 64;
    const long long PS2 = (long long)Bq * Nq * 32;

    const int tid = threadIdx.x;
    for (int idx = tid; idx < 3072; idx += 256) {
        int k = idx / 96, r = idx % 96, p = r >> 5, l = r & 31;
        const float* W0 = W8 + (2 * p) * (Fq * 2 * Fq) + k * (2 * Fq);
        const float* W1 = W8 + (2 * p + 1) * (Fq * 2 * Fq) + k * (2 * Fq);
        Wp[idx] = make_float4(W0[l], W0[l + 32], W1[l], W1[l + 32]);
    }
    if (tid < 96) {
        int p = tid >> 5, l = tid & 31;
        bp[tid] = make_float4(bias8[(2 * p) * 64 + l], bias8[(2 * p) * 64 + 32 + l],
                              bias8[(2 * p + 1) * 64 + l], bias8[(2 * p + 1) * 64 + 32 + l]);
    }
    __syncthreads();

    const int w = tid >> 5, l = tid & 31;
    const int nrows = Bq * Nq;
#pragma unroll 1
    for (int r0 = blockIdx.x * 32 + w * 4; r0 < nrows; r0 += gridDim.x * 32) {
        float y2[4], ym[4];
#pragma unroll
        for (int i = 0; i < 4; i++) {
            int row = r0 + i;
            y2[i] = g_Y2[(size_t)row * 32 + l] + g_Y2[PS2 + (size_t)row * 32 + l];
            ym[i] = g_Y1[(size_t)row * 64 + 32 + l] + g_Y1[PS1 + (size_t)row * 64 + 32 + l];
        }

        float acc[4][3][4];
#pragma unroll
        for (int i = 0; i < 4; i++)
#pragma unroll
            for (int p = 0; p < 3; p++)
#pragma unroll
                for (int q = 0; q < 4; q++) acc[i][p][q] = 0.0f;

#pragma unroll
        for (int k = 0; k < 32; k++) {
            float yk2[4], ykm[4];
#pragma unroll
            for (int i = 0; i < 4; i++) {
                yk2[i] = __shfl_sync(0xffffffffu, y2[i], k);
                ykm[i] = __shfl_sync(0xffffffffu, ym[i], k);
            }
#pragma unroll
            for (int p = 0; p < 3; p++) {
                float4 wv = Wp[k * 96 + p * 32 + l];
#pragma unroll
                for (int i = 0; i < 4; i++) {
                    acc[i][p][0] = fmaf(yk2[i], wv.x, acc[i][p][0]);
                    acc[i][p][1] = fmaf(yk2[i], wv.y, acc[i][p][1]);
                    acc[i][p][2] = fmaf(ykm[i], wv.z, acc[i][p][2]);
                    acc[i][p][3] = fmaf(ykm[i], wv.w, acc[i][p][3]);
                }
            }
        }

#pragma unroll
        for (int i = 0; i < 4; i++) {
            int row = r0 + i;
            int b = row >> 12, n = row & (Nq - 1);
            float s[3];
#pragma unroll
            for (int p = 0; p < 3; p++) {
                float4 bb = bp[p * 32 + l];
                float gx = (acc[i][p][0] + bb.x) * sigf(acc[i][p][1] + bb.y);
                float gh = (acc[i][p][2] + bb.z) * sigf(acc[i][p][3] + bb.w);
                s[p] = gx + gh;
            }
            float i2 = sigf(s[0]);
            float gg = sigf(s[1]);
            float o2 = sigf(s[2]);
            size_t ci = (size_t)row * Fq + l;
            float mo = g_m[ci];
            float mn = i2 * mo + (1.0f - i2) * gg;
            float hn = mn * o2;
            g_m[ci] = mn;
            g_St[((size_t)b * 64 + l) * Nq + n]      = __float2half(hn);
            g_St[((size_t)b * 64 + 32 + l) * Nq + n] = __float2half(mn);
            hidden[(((size_t)b * Tq + t) * Nq + n) * Fq + l] = hn;
            if (t == Tq - 1) {
                last_h[ci] = hn;
                last_m[ci] = mn;
            }
        }
    }
}

// ---------------------------------------------------------------------------
// kernel_launch — R8/R10 structure: one side stream for precompute (passes
// the allocation guard), events join per t-pair.
// ---------------------------------------------------------------------------
extern "C" void kernel_launch(void* const* d_in, const int* in_sizes, int n_in,
                              void* d_out, int out_size) {
    (void)in_sizes; (void)n_in; (void)out_size;
    const float* x    = (const float*)d_in[0];
    const float* adj  = (const float*)d_in[1];
    const float* W    = (const float*)d_in[2];
    const float* bias = (const float*)d_in[3];

    float* hidden = (float*)d_out;
    float* last_h = hidden + (size_t)Bq * Tq * Nq * Fq;
    float* last_c = last_h + (size_t)Bq * Nq * Fq;
    float* last_m = last_c + (size_t)Bq * Nq * Fq;

    float *pYX, *pY1, *pY2;
    __half *pxt, *pSt, *pht;
    cudaGetSymbolAddress((void**)&pYX, g_YX);
    cudaGetSymbolAddress((void**)&pY1, g_Y1);
    cudaGetSymbolAddress((void**)&pY2, g_Y2);
    cudaGetSymbolAddress((void**)&pxt, g_xt);
    cudaGetSymbolAddress((void**)&pSt, g_St);
    cudaGetSymbolAddress((void**)&pht, g_ht);

    const int G1_SMEM = (16384 + 512) * 4;
    const int G2_SMEM = (12288 + 384) * 4;
    const int GEMM64_SMEM = 4 * (128 * 80 + 64 * 80);  // 61440
    const int GEMM32_SMEM = 4 * (128 * 80 + 32 * 80);  // 51200

    static bool inited = false;
    static cudaStream_t s2;
    static cudaEvent_t evFork, evPre[6];
    if (!inited) {
        cudaFuncSetAttribute(gates1_kernel, cudaFuncAttributeMaxDynamicSharedMemorySize, G1_SMEM);
        cudaFuncSetAttribute(gates2_kernel, cudaFuncAttributeMaxDynamicSharedMemorySize, G2_SMEM);
        cudaFuncSetAttribute((void*)adj_gemm_mma<64>,
                             cudaFuncAttributeMaxDynamicSharedMemorySize, GEMM64_SMEM);
        cudaFuncSetAttribute((void*)adj_gemm_mma<32>,
                             cudaFuncAttributeMaxDynamicSharedMemorySize, GEMM32_SMEM);
        cudaStreamCreateWithFlags(&s2, cudaStreamNonBlocking);
        cudaEventCreateWithFlags(&evFork, cudaEventDisableTiming);
        for (int p = 0; p < 6; p++)
            cudaEventCreateWithFlags(&evPre[p], cudaEventDisableTiming);
        inited = true;
    }

    cudaStream_t s0 = 0;

    convert_adj<<<(Bq * Nq * Nq / 4) / 256, 256, 0, s0>>>(adj);
    init_state<<<(Bq * 2 * Fq * Nq + 255) / 256, 256, 0, s0>>>();
    trans_x<<<dim3(Nq / 64, 1, Bq * Tq), 256, 0, s0>>>(x, pxt);

    // Fork: precompute adj @ x on side stream, 6 per-t-pair pieces.
    cudaEventRecord(evFork, s0);
    cudaStreamWaitEvent(s2, evFork, 0);
    for (int p = 0; p < 6; p++) {
        adj_gemm_mma<64><<<dim3(Nq / 128, 1, Bq), 256, GEMM64_SMEM, s2>>>(
            pxt + (size_t)p * 64 * Nq,
            (long long)Tq * Fq * Nq, 1,
            pYX + (size_t)p * 2 * Nq * Fq, (long long)Tq * Nq * Fq,
            32, (long long)Nq * 32, 0LL, Nq / 32);
        cudaEventRecord(evPre[p], s2);
    }

    const long long PS1 = (long long)Bq * Nq * 64;
    const long long PS2 = (long long)Bq * Nq * 32;
    for (int t = 0; t < Tq; t++) {
        // Y1 = adj @ [h|m]^T   (split-K=2)
        adj_gemm_mma<64><<<dim3(Nq / 128, 2, Bq), 256, GEMM64_SMEM, s0>>>(
            pSt, (long long)64 * Nq, 1, pY1, (long long)Nq * 64,
            64, 32LL, PS1, Nq / 64);
        if ((t & 1) == 0) cudaStreamWaitEvent(s0, evPre[t >> 1], 0);
        gates1_kernel<<<128, 256, G1_SMEM, s0>>>(W, bias, t, last_c);
        // Y2 = adj @ h_mid^T   (split-K=2)
        adj_gemm_mma<32><<<dim3(Nq / 128, 2, Bq), 256, GEMM32_SMEM, s0>>>(
            pht, (long long)32 * Nq, 1, pY2, (long long)Nq * 32,
            32, 32LL, PS2, Nq / 64);
        gates2_kernel<<<128, 256, G2_SMEM, s0>>>(W + 8 * (Fq * 2 * Fq), bias + 8 * (2 * Fq),
                                                 t, hidden, last_h, last_m);
    }
}

// round 12
// speedup vs baseline: 3.1458x; 1.0137x over previous
#include <cuda_runtime.h>
#include <cuda_fp16.h>
#include <cstdint>

#define Bq 4
#define Tq 12
#define Nq 4096
#define Fq 32

// ---------------------------------------------------------------------------
// PTX helpers — Ampere-era only (compute_103-safe: tcgen05 rejected by ptxas
// at the compute_103 virtual arch; s8 IMMA slow (R5); term-major order slow
// (R6); per-batch multi-stream graphs trip the upload-residue guard (R9)).
// ---------------------------------------------------------------------------
__device__ __forceinline__ uint32_t smem_to_u32(const void* p) {
    uint32_t a;
    asm("{ .reg .u64 t; cvta.to.shared.u64 t, %1; cvt.u32.u64 %0, t; }" : "=r"(a) : "l"(p));
    return a;
}

#define CP_ASYNC16(dst, src) \
    asm volatile("cp.async.cg.shared.global [%0], [%1], 16;" :: "r"(dst), "l"(src) : "memory")
#define CP_COMMIT() asm volatile("cp.async.commit_group;" ::: "memory")
#define CP_WAIT0()  asm volatile("cp.async.wait_group 0;" ::: "memory")
#define CP_WAIT1()  asm volatile("cp.async.wait_group 1;" ::: "memory")

__device__ __forceinline__ void ldsm4(uint32_t addr, uint32_t* r) {
    asm volatile("ldmatrix.sync.aligned.m8n8.x4.shared.b16 {%0,%1,%2,%3}, [%4];"
                 : "=r"(r[0]), "=r"(r[1]), "=r"(r[2]), "=r"(r[3]) : "r"(addr));
}
__device__ __forceinline__ void mma_f16(float* d, const uint32_t* a, uint32_t b0, uint32_t b1) {
    asm volatile("mma.sync.aligned.m16n8k16.row.col.f32.f16.f16.f32 "
                 "{%0,%1,%2,%3},{%4,%5,%6,%7},{%8,%9},{%0,%1,%2,%3};"
                 : "+f"(d[0]), "+f"(d[1]), "+f"(d[2]), "+f"(d[3])
                 : "r"(a[0]), "r"(a[1]), "r"(a[2]), "r"(a[3]), "r"(b0), "r"(b1));
}

// ---------------------------------------------------------------------------
// Device scratch (single fp16 operands — R11 error model)
// ---------------------------------------------------------------------------
__device__ __align__(128) __half g_Ah[(size_t)Bq * Nq * Nq];
__device__ __align__(128) __half g_xt[(size_t)Bq * Tq * Fq * Nq];   // [b][t*32+f][n]
__device__ __align__(128) __half g_St[(size_t)Bq * 2 * Fq * Nq];    // [b][64][n]  (h|m)
__device__ __align__(128) __half g_ht[(size_t)Bq * Fq * Nq];        // [b][32][n]  (h_mid)

__device__ __align__(128) float g_YX[(size_t)Bq * Tq * Nq * Fq];
__device__ __align__(128) float g_Y1[4 * (size_t)Bq * Nq * 2 * Fq]; // split-K=4 partials
__device__ __align__(128) float g_Y2[4 * (size_t)Bq * Nq * Fq];
__device__ __align__(128) float g_m [(size_t)Bq * Nq * Fq];
__device__ __align__(128) float g_c [(size_t)Bq * Nq * Fq];

__device__ __forceinline__ float sigf(float x) { return 1.0f / (1.0f + __expf(-x)); }

// ---------------------------------------------------------------------------
// adj -> fp16
// ---------------------------------------------------------------------------
__global__ __launch_bounds__(256) void convert_adj(const float* __restrict__ adj) {
    size_t i = (size_t)blockIdx.x * 256 + threadIdx.x;
    float4 v = ((const float4*)adj)[i];
    __half2 p0 = __floats2half2_rn(v.x, v.y);
    __half2 p1 = __floats2half2_rn(v.z, v.w);
    uint2 w;
    w.x = *(uint32_t*)&p0; w.y = *(uint32_t*)&p1;
    ((uint2*)g_Ah)[i] = w;
}

__global__ void init_state() {
    int i = blockIdx.x * blockDim.x + threadIdx.x;
    if (i < Bq * Nq * Fq) { g_m[i] = 1.0f; g_c[i] = 1.0f; }
    if (i < Bq * 2 * Fq * Nq) g_St[i] = __float2half(1.0f);
}

// ---------------------------------------------------------------------------
// transpose x: [z][4096][32] fp32 -> [z][32][4096] fp16
// ---------------------------------------------------------------------------
__global__ __launch_bounds__(256) void trans_x(const float* __restrict__ V,
                                               __half* __restrict__ T) {
    __shared__ float tile[64][33];
    const int z = blockIdx.z;
    const int n0 = blockIdx.x * 64;
    const float* v = V + (size_t)z * Nq * 32 + (size_t)n0 * 32;
    const int tid = threadIdx.x;
#pragma unroll
    for (int idx = tid; idx < 64 * 32; idx += 256)
        tile[idx >> 5][idx & 31] = v[idx];
    __syncthreads();
    __half* t = T + (size_t)z * 32 * Nq;
#pragma unroll
    for (int idx = tid; idx < 64 * 32; idx += 256) {
        int f = idx >> 6, j = idx & 63;
        t[(size_t)f * Nq + n0 + j] = __float2half(tile[j][f]);
    }
}

// ---------------------------------------------------------------------------
// fp16 mma.sync GEMM, SUPERCHUNK (K=64 per barrier, two 32-k sub-chunks),
// 3 superbuffers, one commit + one __syncthreads per superchunk (R4-proven
// reuse logic: barrier at s proves compute(s-1) done; issue(s+2) writes
// buffer (s+2)%3 == (s-1)%3).
//   Y[part=blockIdx.y][z] = adj[z/adiv][kseg] @ V[z][kseg]
// BM=128, 8 warps 4(m) x 2(n), fp32 accumulators, 2 CTAs/SM.
// ---------------------------------------------------------------------------
template <int BN>
__global__ __launch_bounds__(256, 2) void adj_gemm_mma(
    const __half* __restrict__ B_g,
    long long bZ, int adiv, float* __restrict__ Y, long long yZ,
    int rstride, long long gstride, long long partStride, int nss) {
    constexpr int RB = 80;                 // 64B data + 16B pad
    constexpr int A_BYTES = 128 * RB;      // 10240
    constexpr int B_BYTES = BN * RB;
    constexpr int OFF_B = A_BYTES;
    constexpr int SUB   = A_BYTES + B_BYTES;   // one 32-k sub-chunk
    constexpr int STAGE = 2 * SUB;             // superchunk (K=64)
    constexpr int WN = BN / 2;
    constexpr int NF = WN / 8;
    constexpr int NB = (NF + 1) / 2;

    extern __shared__ char smc[];
    const uint32_t sbase = smem_to_u32(smc);
    const int tid = threadIdx.x;
    const int wid = tid >> 5, lane = tid & 31;
    const int wm = wid & 3, wn = wid >> 2;
    const int z = blockIdx.z;
    const int m0 = blockIdx.x * 128;
    const int kbase = blockIdx.y * nss * 64;

    const __half* gA = g_Ah + (size_t)(z / adiv) * Nq * Nq + (size_t)m0 * Nq + kbase;
    const __half* gB = B_g + (size_t)z * bZ + kbase;

    const int arow = tid >> 2;             // 0..63, +64 for rep 1
    const int acol = tid & 3;
    const int brow = (BN == 64) ? (tid >> 2) : ((tid & 127) >> 2);
    const bool bact = (BN == 64) || (tid < 128);

    float acc[2][NF][4];
#pragma unroll
    for (int mf = 0; mf < 2; mf++)
#pragma unroll
        for (int nf = 0; nf < NF; nf++)
#pragma unroll
            for (int q = 0; q < 4; q++) acc[mf][nf][q] = 0.0f;

    auto issue = [&](int s) {
        const uint32_t st = sbase + (uint32_t)(s % 3) * STAGE;
#pragma unroll
        for (int kc = 0; kc < 2; kc++) {
            const uint32_t sb = st + kc * SUB;
            const int k0 = s * 64 + kc * 32;
#pragma unroll
            for (int rep = 0; rep < 2; rep++) {
                int r = rep * 64 + arow;
                CP_ASYNC16(sb + r * RB + acol * 16, gA + (size_t)r * Nq + k0 + acol * 8);
            }
            if (bact)
                CP_ASYNC16(sb + OFF_B + brow * RB + acol * 16,
                           gB + (size_t)brow * Nq + k0 + acol * 8);
        }
    };

    issue(0); CP_COMMIT();
    issue(1); CP_COMMIT();

    const int a_r = (lane & 15);
    const int a_k = (lane >> 4) * 16;
    const int b_r = ((lane >> 4) << 3) + (lane & 7);
    const int b_k = ((lane >> 3) & 1) * 16;

#pragma unroll 1
    for (int s = 0; s < nss; s++) {
        if (s + 1 < nss) { CP_WAIT1(); } else { CP_WAIT0(); }
        __syncthreads();
        if (s + 2 < nss) { issue(s + 2); CP_COMMIT(); }

        const uint32_t st = sbase + (uint32_t)(s % 3) * STAGE;
#pragma unroll
        for (int kc = 0; kc < 2; kc++) {
            const uint32_t sb = st + kc * SUB;
#pragma unroll
            for (int ks = 0; ks < 2; ks++) {
                uint32_t ah[2][4];
#pragma unroll
                for (int mf = 0; mf < 2; mf++) {
                    uint32_t addr = sb + (wm * 32 + mf * 16 + a_r) * RB + ks * 32 + a_k;
                    ldsm4(addr, ah[mf]);
                }
                uint32_t bh[NB][4];
#pragma unroll
                for (int nb = 0; nb < NB; nb++) {
                    uint32_t addr = sb + OFF_B + (wn * WN + nb * 16 + b_r) * RB + ks * 32 + b_k;
                    ldsm4(addr, bh[nb]);
                }
#pragma unroll
                for (int mf = 0; mf < 2; mf++)
#pragma unroll
                    for (int nf = 0; nf < NF; nf++) {
                        const int nb = nf >> 1, pr = (nf & 1) * 2;
                        mma_f16(acc[mf][nf], ah[mf], bh[nb][pr], bh[nb][pr + 1]);
                    }
            }
        }
    }

    float* yb = Y + (size_t)blockIdx.y * partStride + (size_t)z * yZ;
#pragma unroll
    for (int mf = 0; mf < 2; mf++)
#pragma unroll
        for (int nf = 0; nf < NF; nf++) {
            int r = m0 + wm * 32 + mf * 16 + (lane >> 2);
            int cj = wn * WN + nf * 8 + (lane & 3) * 2;
            size_t off = (size_t)(cj >> 5) * gstride + (cj & 31);
            float* o0 = yb + (size_t)r * rstride + off;
            float* o1 = yb + (size_t)(r + 8) * rstride + off;
            *(float2*)o0 = make_float2(acc[mf][nf][0], acc[mf][nf][1]);
            *(float2*)o1 = make_float2(acc[mf][nf][2], acc[mf][nf][3]);
        }
}

// ---------------------------------------------------------------------------
// gates1: LSTM gates 0..7, row-blocked; sums 4 split-K partials; writes
// h_mid transposed fp16.
// ---------------------------------------------------------------------------
__global__ __launch_bounds__(256) void gates1_kernel(const float* __restrict__ W,
                                                     const float* __restrict__ bias,
                                                     int t, float* __restrict__ last_c) {
    extern __shared__ float sm[];
    float4* Wp = (float4*)sm;
    float4* bp = (float4*)(sm + 16384);
    const long long PS1 = (long long)Bq * Nq * 64;

    const int tid = threadIdx.x;
    for (int idx = tid; idx < 4096; idx += 256) {
        int l = idx & 31, p = (idx >> 5) & 3, k = idx >> 7;
        const float* W0 = W + (2 * p) * (Fq * 2 * Fq) + k * (2 * Fq);
        const float* W1 = W + (2 * p + 1) * (Fq * 2 * Fq) + k * (2 * Fq);
        Wp[idx] = make_float4(W0[l], W0[l + 32], W1[l], W1[l + 32]);
    }
    if (tid < 128) {
        int l = tid & 31, p = tid >> 5;
        bp[p * 32 + l] = make_float4(bias[(2 * p) * 64 + l], bias[(2 * p) * 64 + 32 + l],
                                     bias[(2 * p + 1) * 64 + l], bias[(2 * p + 1) * 64 + 32 + l]);
    }
    __syncthreads();

    const int w = tid >> 5, l = tid & 31;
    const int nrows = Bq * Nq;
#pragma unroll 1
    for (int r0 = blockIdx.x * 32 + w * 4; r0 < nrows; r0 += gridDim.x * 32) {
        float yx[4], yh[4];
#pragma unroll
        for (int i = 0; i < 4; i++) {
            int row = r0 + i;
            int b = row >> 12, n = row & (Nq - 1);
            yx[i] = g_YX[(((size_t)b * Tq + t) * Nq + n) * Fq + l];
            float s = 0.f;
#pragma unroll
            for (int p = 0; p < 4; p++) s += g_Y1[p * PS1 + (size_t)row * 64 + l];
            yh[i] = s;
        }

        float acc[4][4][4];
#pragma unroll
        for (int i = 0; i < 4; i++)
#pragma unroll
            for (int p = 0; p < 4; p++)
#pragma unroll
                for (int q = 0; q < 4; q++) acc[i][p][q] = 0.0f;

#pragma unroll
        for (int k = 0; k < 32; k++) {
            float ykx[4], ykh[4];
#pragma unroll
            for (int i = 0; i < 4; i++) {
                ykx[i] = __shfl_sync(0xffffffffu, yx[i], k);
                ykh[i] = __shfl_sync(0xffffffffu, yh[i], k);
            }
#pragma unroll
            for (int p = 0; p < 4; p++) {
                float4 wv = Wp[k * 128 + p * 32 + l];
#pragma unroll
                for (int i = 0; i < 4; i++) {
                    acc[i][p][0] = fmaf(ykx[i], wv.x, acc[i][p][0]);
                    acc[i][p][1] = fmaf(ykx[i], wv.y, acc[i][p][1]);
                    acc[i][p][2] = fmaf(ykh[i], wv.z, acc[i][p][2]);
                    acc[i][p][3] = fmaf(ykh[i], wv.w, acc[i][p][3]);
                }
            }
        }

#pragma unroll
        for (int i = 0; i < 4; i++) {
            int row = r0 + i;
            int b = row >> 12, n = row & (Nq - 1);
            float s[4];
#pragma unroll
            for (int p = 0; p < 4; p++) {
                float4 bb = bp[p * 32 + l];
                float gx = (acc[i][p][0] + bb.x) * sigf(acc[i][p][1] + bb.y);
                float gh = (acc[i][p][2] + bb.z) * sigf(acc[i][p][3] + bb.w);
                s[p] = gx + gh;
            }
            float f  = sigf(s[0]);
            float ig = sigf(s[1]);
            float o  = sigf(s[3]);
            size_t ci = (size_t)row * Fq + l;
            float cn = f * g_c[ci] + ig * tanhf(s[2]);
            g_c[ci] = cn;
            float hm = o * tanhf(cn);
            g_ht[((size_t)b * Fq + l) * Nq + n] = __float2half(hm);
            if (t == Tq - 1) last_c[ci] = cn;
        }
    }
}

// ---------------------------------------------------------------------------
// gates2: memory gates 8..13, row-blocked; sums 4 split-K partials; writes
// new [h|m] transposed fp16.
// ---------------------------------------------------------------------------
__global__ __launch_bounds__(256) void gates2_kernel(const float* __restrict__ W8,
                                                     const float* __restrict__ bias8,
                                                     int t, float* __restrict__ hidden,
                                                     float* __restrict__ last_h,
                                                     float* __restrict__ last_m) {
    extern __shared__ float sm[];
    float4* Wp = (float4*)sm;
    float4* bp = (float4*)(sm + 12288);
    const long long PS1 = (long long)Bq * Nq * 64;
    const long long PS2 = (long long)Bq * Nq * 32;

    const int tid = threadIdx.x;
    for (int idx = tid; idx < 3072; idx += 256) {
        int k = idx / 96, r = idx % 96, p = r >> 5, l = r & 31;
        const float* W0 = W8 + (2 * p) * (Fq * 2 * Fq) + k * (2 * Fq);
        const float* W1 = W8 + (2 * p + 1) * (Fq * 2 * Fq) + k * (2 * Fq);
        Wp[idx] = make_float4(W0[l], W0[l + 32], W1[l], W1[l + 32]);
    }
    if (tid < 96) {
        int p = tid >> 5, l = tid & 31;
        bp[tid] = make_float4(bias8[(2 * p) * 64 + l], bias8[(2 * p) * 64 + 32 + l],
                              bias8[(2 * p + 1) * 64 + l], bias8[(2 * p + 1) * 64 + 32 + l]);
    }
    __syncthreads();

    const int w = tid >> 5, l = tid & 31;
    const int nrows = Bq * Nq;
#pragma unroll 1
    for (int r0 = blockIdx.x * 32 + w * 4; r0 < nrows; r0 += gridDim.x * 32) {
        float y2[4], ym[4];
#pragma unroll
        for (int i = 0; i < 4; i++) {
            int row = r0 + i;
            float a2 = 0.f, am = 0.f;
#pragma unroll
            for (int p = 0; p < 4; p++) {
                a2 += g_Y2[p * PS2 + (size_t)row * 32 + l];
                am += g_Y1[p * PS1 + (size_t)row * 64 + 32 + l];
            }
            y2[i] = a2; ym[i] = am;
        }

        float acc[4][3][4];
#pragma unroll
        for (int i = 0; i < 4; i++)
#pragma unroll
            for (int p = 0; p < 3; p++)
#pragma unroll
                for (int q = 0; q < 4; q++) acc[i][p][q] = 0.0f;

#pragma unroll
        for (int k = 0; k < 32; k++) {
            float yk2[4], ykm[4];
#pragma unroll
            for (int i = 0; i < 4; i++) {
                yk2[i] = __shfl_sync(0xffffffffu, y2[i], k);
                ykm[i] = __shfl_sync(0xffffffffu, ym[i], k);
            }
#pragma unroll
            for (int p = 0; p < 3; p++) {
                float4 wv = Wp[k * 96 + p * 32 + l];
#pragma unroll
                for (int i = 0; i < 4; i++) {
                    acc[i][p][0] = fmaf(yk2[i], wv.x, acc[i][p][0]);
                    acc[i][p][1] = fmaf(yk2[i], wv.y, acc[i][p][1]);
                    acc[i][p][2] = fmaf(ykm[i], wv.z, acc[i][p][2]);
                    acc[i][p][3] = fmaf(ykm[i], wv.w, acc[i][p][3]);
                }
            }
        }

#pragma unroll
        for (int i = 0; i < 4; i++) {
            int row = r0 + i;
            int b = row >> 12, n = row & (Nq - 1);
            float s[3];
#pragma unroll
            for (int p = 0; p < 3; p++) {
                float4 bb = bp[p * 32 + l];
                float gx = (acc[i][p][0] + bb.x) * sigf(acc[i][p][1] + bb.y);
                float gh = (acc[i][p][2] + bb.z) * sigf(acc[i][p][3] + bb.w);
                s[p] = gx + gh;
            }
            float i2 = sigf(s[0]);
            float gg = sigf(s[1]);
            float o2 = sigf(s[2]);
            size_t ci = (size_t)row * Fq + l;
            float mo = g_m[ci];
            float mn = i2 * mo + (1.0f - i2) * gg;
            float hn = mn * o2;
            g_m[ci] = mn;
            g_St[((size_t)b * 64 + l) * Nq + n]      = __float2half(hn);
            g_St[((size_t)b * 64 + 32 + l) * Nq + n] = __float2half(mn);
            hidden[(((size_t)b * Tq + t) * Nq + n) * Fq + l] = hn;
            if (t == Tq - 1) {
                last_h[ci] = hn;
                last_m[ci] = mn;
            }
        }
    }
}

// ---------------------------------------------------------------------------
// kernel_launch — R8/R10/R11 structure: one side stream for precompute,
// per-t-pair event joins.
// ---------------------------------------------------------------------------
extern "C" void kernel_launch(void* const* d_in, const int* in_sizes, int n_in,
                              void* d_out, int out_size) {
    (void)in_sizes; (void)n_in; (void)out_size;
    const float* x    = (const float*)d_in[0];
    const float* adj  = (const float*)d_in[1];
    const float* W    = (const float*)d_in[2];
    const float* bias = (const float*)d_in[3];

    float* hidden = (float*)d_out;
    float* last_h = hidden + (size_t)Bq * Tq * Nq * Fq;
    float* last_c = last_h + (size_t)Bq * Nq * Fq;
    float* last_m = last_c + (size_t)Bq * Nq * Fq;

    float *pYX, *pY1, *pY2;
    __half *pxt, *pSt, *pht;
    cudaGetSymbolAddress((void**)&pYX, g_YX);
    cudaGetSymbolAddress((void**)&pY1, g_Y1);
    cudaGetSymbolAddress((void**)&pY2, g_Y2);
    cudaGetSymbolAddress((void**)&pxt, g_xt);
    cudaGetSymbolAddress((void**)&pSt, g_St);
    cudaGetSymbolAddress((void**)&pht, g_ht);

    const int G1_SMEM = (16384 + 512) * 4;
    const int G2_SMEM = (12288 + 384) * 4;
    const int GEMM64_SMEM = 3 * 2 * (128 * 80 + 64 * 80);  // 92160
    const int GEMM32_SMEM = 3 * 2 * (128 * 80 + 32 * 80);  // 76800

    static bool inited = false;
    static cudaStream_t s2;
    static cudaEvent_t evFork, evPre[6];
    if (!inited) {
        cudaFuncSetAttribute(gates1_kernel, cudaFuncAttributeMaxDynamicSharedMemorySize, G1_SMEM);
        cudaFuncSetAttribute(gates2_kernel, cudaFuncAttributeMaxDynamicSharedMemorySize, G2_SMEM);
        cudaFuncSetAttribute((void*)adj_gemm_mma<64>,
                             cudaFuncAttributeMaxDynamicSharedMemorySize, GEMM64_SMEM);
        cudaFuncSetAttribute((void*)adj_gemm_mma<32>,
                             cudaFuncAttributeMaxDynamicSharedMemorySize, GEMM32_SMEM);
        cudaStreamCreateWithFlags(&s2, cudaStreamNonBlocking);
        cudaEventCreateWithFlags(&evFork, cudaEventDisableTiming);
        for (int p = 0; p < 6; p++)
            cudaEventCreateWithFlags(&evPre[p], cudaEventDisableTiming);
        inited = true;
    }

    cudaStream_t s0 = 0;

    convert_adj<<<(Bq * Nq * Nq / 4) / 256, 256, 0, s0>>>(adj);
    init_state<<<(Bq * 2 * Fq * Nq + 255) / 256, 256, 0, s0>>>();
    trans_x<<<dim3(Nq / 64, 1, Bq * Tq), 256, 0, s0>>>(x, pxt);

    // Fork: precompute adj @ x on side stream, 6 per-t-pair pieces (full K).
    cudaEventRecord(evFork, s0);
    cudaStreamWaitEvent(s2, evFork, 0);
    for (int p = 0; p < 6; p++) {
        adj_gemm_mma<64><<<dim3(Nq / 128, 1, Bq), 256, GEMM64_SMEM, s2>>>(
            pxt + (size_t)p * 64 * Nq,
            (long long)Tq * Fq * Nq, 1,
            pYX + (size_t)p * 2 * Nq * Fq, (long long)Tq * Nq * Fq,
            32, (long long)Nq * 32, 0LL, Nq / 64);
        cudaEventRecord(evPre[p], s2);
    }

    const long long PS1 = (long long)Bq * Nq * 64;
    const long long PS2 = (long long)Bq * Nq * 32;
    for (int t = 0; t < Tq; t++) {
        // Y1 = adj @ [h|m]^T   (split-K=4, 16 superchunks each)
        adj_gemm_mma<64><<<dim3(Nq / 128, 4, Bq), 256, GEMM64_SMEM, s0>>>(
            pSt, (long long)64 * Nq, 1, pY1, (long long)Nq * 64,
            64, 32LL, PS1, Nq / 256);
        if ((t & 1) == 0) cudaStreamWaitEvent(s0, evPre[t >> 1], 0);
        gates1_kernel<<<128, 256, G1_SMEM, s0>>>(W, bias, t, last_c);
        // Y2 = adj @ h_mid^T   (split-K=4)
        adj_gemm_mma<32><<<dim3(Nq / 128, 4, Bq), 256, GEMM32_SMEM, s0>>>(
            pht, (long long)32 * Nq, 1, pY2, (long long)Nq * 32,
            32, 32LL, PS2, Nq / 256);
        gates2_kernel<<<128, 256, G2_SMEM, s0>>>(W + 8 * (Fq * 2 * Fq), bias + 8 * (2 * Fq),
                                                 t, hidden, last_h, last_m);
    }
}